// round 1
// baseline (speedup 1.0000x reference)
#include <cuda_runtime.h>
#include <cstddef>

// Problem constants (B=4, T=2048, C=2048, H=16, D=128)
#define B_  4
#define T_  2048
#define C_  2048
#define H_  16
#define D_  128
#define M_  (B_ * T_)       // 8192 rows
#define N1_ (3 * C_)        // 6144 qkv cols

// Scratch (alloc-free rule: __device__ globals)
__device__ float g_qkv[(size_t)M_ * N1_];   // [8192, 6144]  ~201 MB
__device__ float g_att[(size_t)M_ * C_];    // [8192, 2048]  ~67 MB

// ---------------------------------------------------------------------------
// SGEMM: C[M,N] = A[M,K] @ B[K,N] + bias[N]
// 128x128 tile, BK=16, 256 threads, 8x8 per-thread microkernel.
// Requires M%128==0, N%128==0, K%16==0 (true for all our shapes).
// ---------------------------------------------------------------------------
__global__ __launch_bounds__(256, 2)
void gemm_bias_kernel(const float* __restrict__ A, const float* __restrict__ Bm,
                      const float* __restrict__ bias, float* __restrict__ Cm,
                      int M, int N, int K)
{
    const int BK  = 16;
    const int LDA = 132;                     // padded stride for transposed A tile
    __shared__ __align__(16) float sA[16 * 132];
    __shared__ __align__(16) float sB[16 * 128];

    const int tid = threadIdx.x;
    const int tx  = tid & 15;                // 0..15 -> 8 cols each
    const int ty  = tid >> 4;                // 0..15 -> 8 rows each
    const int m0  = blockIdx.y * 128;
    const int n0  = blockIdx.x * 128;

    const float* Ab = A + (size_t)m0 * K;
    const float* Bb = Bm + n0;

    float acc[8][8];
#pragma unroll
    for (int i = 0; i < 8; i++)
#pragma unroll
        for (int j = 0; j < 8; j++) acc[i][j] = 0.f;

    for (int k0 = 0; k0 < K; k0 += BK) {
        // Load A tile (128 x 16), store transposed into sA[k][m]
#pragma unroll
        for (int l = 0; l < 2; l++) {
            int f   = tid + l * 256;         // 0..511 float4 slots
            int row = f >> 2;                // 0..127
            int kc  = (f & 3) << 2;          // 0,4,8,12
            float4 v = *(const float4*)(Ab + (size_t)row * K + k0 + kc);
            sA[(kc + 0) * LDA + row] = v.x;
            sA[(kc + 1) * LDA + row] = v.y;
            sA[(kc + 2) * LDA + row] = v.z;
            sA[(kc + 3) * LDA + row] = v.w;
        }
        // Load B tile (16 x 128) directly
#pragma unroll
        for (int l = 0; l < 2; l++) {
            int f  = tid + l * 256;
            int kr = f >> 5;                 // 0..15
            int nc = (f & 31) << 2;          // 0..124
            *(float4*)(sB + kr * 128 + nc) =
                *(const float4*)(Bb + (size_t)(k0 + kr) * N + nc);
        }
        __syncthreads();

#pragma unroll
        for (int k = 0; k < BK; k++) {
            float a[8], b[8];
            *(float4*)&a[0] = *(const float4*)(sA + k * LDA + ty * 8);
            *(float4*)&a[4] = *(const float4*)(sA + k * LDA + ty * 8 + 4);
            *(float4*)&b[0] = *(const float4*)(sB + k * 128 + tx * 8);
            *(float4*)&b[4] = *(const float4*)(sB + k * 128 + tx * 8 + 4);
#pragma unroll
            for (int i = 0; i < 8; i++)
#pragma unroll
                for (int j = 0; j < 8; j++)
                    acc[i][j] += a[i] * b[j];
        }
        __syncthreads();
    }

    // Epilogue: add bias, store
    float bi[8];
    *(float4*)&bi[0] = *(const float4*)(bias + n0 + tx * 8);
    *(float4*)&bi[4] = *(const float4*)(bias + n0 + tx * 8 + 4);

    float* Cr = Cm + (size_t)(m0 + ty * 8) * N + n0 + tx * 8;
#pragma unroll
    for (int i = 0; i < 8; i++) {
        float4 r0, r1;
        r0.x = acc[i][0] + bi[0]; r0.y = acc[i][1] + bi[1];
        r0.z = acc[i][2] + bi[2]; r0.w = acc[i][3] + bi[3];
        r1.x = acc[i][4] + bi[4]; r1.y = acc[i][5] + bi[5];
        r1.z = acc[i][6] + bi[6]; r1.w = acc[i][7] + bi[7];
        *(float4*)(Cr + (size_t)i * N)     = r0;
        *(float4*)(Cr + (size_t)i * N + 4) = r1;
    }
}

// ---------------------------------------------------------------------------
// Causal flash-attention (fp32). One block per (b,h, q-tile of 64 rows).
// BR=BC=64, D=128, 256 threads. Online softmax, only tiles j0 <= i0.
// smem: Qt[128][64] + Kt[128][64] + V[64][128] + P[64][65] + stats = ~113 KB.
// ---------------------------------------------------------------------------
#define BR 64
#define BC 64
#define FLASH_SMEM_FLOATS (128*64 + 128*64 + 64*128 + 64*65 + 3*64)

__global__ __launch_bounds__(256, 1)
void flash_kernel(const float* __restrict__ qkv, float* __restrict__ att)
{
    extern __shared__ __align__(16) float sm[];
    float* sQ = sm;                     // [128][64] (k-major, transposed)
    float* sK = sQ + 128 * 64;          // [128][64]
    float* sV = sK + 128 * 64;          // [64][128]
    float* sP = sV + 64 * 128;          // [64][65]  padded stride
    float* sMx = sP + 64 * 65;          // [64] running max
    float* sL  = sMx + 64;              // [64] running sum
    float* sCo = sL + 64;               // [64] correction factor

    const int tid = threadIdx.x;
    const int tc  = tid & 15;           // 0..15 -> 4 S-cols / 8 O-cols
    const int tr  = tid >> 4;           // 0..15 -> 4 rows
    const int bh  = blockIdx.x;
    const int b   = bh >> 4;
    const int h   = bh & 15;
    const int i0  = (gridDim.y - 1 - blockIdx.y) * BR;  // heavy tiles first

    const size_t RS = (size_t)N1_;      // 6144 qkv row stride
    const float scale = 0.08838834764831844055f;  // 1/sqrt(128)

    const float* qb = qkv + (size_t)(b * T_ + i0) * RS + h * D_;
    const float* kb0 = qkv + (size_t)b * T_ * RS + C_ + h * D_;
    const float* vb0 = qkv + (size_t)b * T_ * RS + 2 * C_ + h * D_;

    // Load Q tile transposed, pre-scaled
#pragma unroll
    for (int l = 0; l < 8; l++) {
        int f  = tid + l * 256;
        int r  = f >> 5;                // 0..63
        int dc = (f & 31) << 2;         // 0..124
        float4 v = *(const float4*)(qb + (size_t)r * RS + dc);
        sQ[(dc + 0) * BR + r] = v.x * scale;
        sQ[(dc + 1) * BR + r] = v.y * scale;
        sQ[(dc + 2) * BR + r] = v.z * scale;
        sQ[(dc + 3) * BR + r] = v.w * scale;
    }
    if (tid < BR) { sMx[tid] = -1e30f; sL[tid] = 0.f; }

    float o[4][8];
#pragma unroll
    for (int i = 0; i < 4; i++)
#pragma unroll
        for (int d = 0; d < 8; d++) o[i][d] = 0.f;

    const int ntiles = i0 / BC + 1;
    for (int jt = 0; jt < ntiles; jt++) {
        const int j0 = jt * BC;
        __syncthreads();  // previous iteration's sV/sP consumers done

        const float* kb = kb0 + (size_t)j0 * RS;
        const float* vb = vb0 + (size_t)j0 * RS;
#pragma unroll
        for (int l = 0; l < 8; l++) {
            int f  = tid + l * 256;
            int r  = f >> 5;
            int dc = (f & 31) << 2;
            float4 v = *(const float4*)(kb + (size_t)r * RS + dc);
            sK[(dc + 0) * BC + r] = v.x;
            sK[(dc + 1) * BC + r] = v.y;
            sK[(dc + 2) * BC + r] = v.z;
            sK[(dc + 3) * BC + r] = v.w;
            float4 w = *(const float4*)(vb + (size_t)r * RS + dc);
            *(float4*)(sV + r * 128 + dc) = w;
        }
        __syncthreads();

        // S = Q @ K^T  (64x64, 4x4 per thread)
        float s[4][4];
#pragma unroll
        for (int i = 0; i < 4; i++)
#pragma unroll
            for (int j = 0; j < 4; j++) s[i][j] = 0.f;
#pragma unroll 8
        for (int k = 0; k < D_; k++) {
            float a[4], c[4];
            *(float4*)a = *(const float4*)(sQ + k * BR + tr * 4);
            *(float4*)c = *(const float4*)(sK + k * BC + tc * 4);
#pragma unroll
            for (int i = 0; i < 4; i++)
#pragma unroll
                for (int j = 0; j < 4; j++)
                    s[i][j] += a[i] * c[j];
        }

        // Causal mask on diagonal tile (j0 == i0 for the last tile)
        if (jt == ntiles - 1) {
#pragma unroll
            for (int i = 0; i < 4; i++)
#pragma unroll
                for (int j = 0; j < 4; j++)
                    if (j0 + tc * 4 + j > i0 + tr * 4 + i) s[i][j] = -1e30f;
        }

#pragma unroll
        for (int i = 0; i < 4; i++)
#pragma unroll
            for (int j = 0; j < 4; j++)
                sP[(tr * 4 + i) * 65 + tc * 4 + j] = s[i][j];
        __syncthreads();

        // Online softmax row stats (one thread per row)
        if (tid < BR) {
            const int r = tid;
            float mold = sMx[r];
            float mx = mold;
#pragma unroll 8
            for (int j = 0; j < BC; j++) mx = fmaxf(mx, sP[r * 65 + j]);
            float corr = __expf(mold - mx);
            float l = sL[r] * corr;
#pragma unroll 8
            for (int j = 0; j < BC; j++) {
                float e = __expf(sP[r * 65 + j] - mx);
                sP[r * 65 + j] = e;
                l += e;
            }
            sMx[r] = mx; sL[r] = l; sCo[r] = corr;
        }
        __syncthreads();

        // Rescale O, accumulate O += P @ V  (each thread: 4 rows x 8 d-cols)
        float cr[4];
#pragma unroll
        for (int i = 0; i < 4; i++) cr[i] = sCo[tr * 4 + i];
#pragma unroll
        for (int i = 0; i < 4; i++)
#pragma unroll
            for (int d = 0; d < 8; d++) o[i][d] *= cr[i];

#pragma unroll 4
        for (int j = 0; j < BC; j++) {
            float p[4];
#pragma unroll
            for (int i = 0; i < 4; i++) p[i] = sP[(tr * 4 + i) * 65 + j];
            float v0[4], v1[4];
            *(float4*)v0 = *(const float4*)(sV + j * 128 + tc * 8);
            *(float4*)v1 = *(const float4*)(sV + j * 128 + tc * 8 + 4);
#pragma unroll
            for (int i = 0; i < 4; i++) {
#pragma unroll
                for (int d = 0; d < 4; d++) {
                    o[i][d]     += p[i] * v0[d];
                    o[i][4 + d] += p[i] * v1[d];
                }
            }
        }
    }

    // Epilogue: normalize and store to g_att[(b,t), h*D + d]
    float* ob = att + (size_t)(b * T_ + i0) * C_ + h * D_;
#pragma unroll
    for (int i = 0; i < 4; i++) {
        float inv = 1.f / sL[tr * 4 + i];
        float4 r0, r1;
        r0.x = o[i][0] * inv; r0.y = o[i][1] * inv;
        r0.z = o[i][2] * inv; r0.w = o[i][3] * inv;
        r1.x = o[i][4] * inv; r1.y = o[i][5] * inv;
        r1.z = o[i][6] * inv; r1.w = o[i][7] * inv;
        *(float4*)(ob + (size_t)(tr * 4 + i) * C_ + tc * 8)     = r0;
        *(float4*)(ob + (size_t)(tr * 4 + i) * C_ + tc * 8 + 4) = r1;
    }
}

// ---------------------------------------------------------------------------
// Launch: QKV GEMM -> flash attention -> proj GEMM. Graph-capturable.
// ---------------------------------------------------------------------------
extern "C" void kernel_launch(void* const* d_in, const int* in_sizes, int n_in,
                              void* d_out, int out_size)
{
    const float* x     = (const float*)d_in[0];
    const float* Wqkv  = (const float*)d_in[1];
    const float* bqkv  = (const float*)d_in[2];
    const float* Wproj = (const float*)d_in[3];
    const float* bproj = (const float*)d_in[4];
    float* out = (float*)d_out;

    float *qkv, *att;
    cudaGetSymbolAddress((void**)&qkv, g_qkv);
    cudaGetSymbolAddress((void**)&att, g_att);

    // 1) qkv = x @ Wqkv + bqkv   [8192,2048]x[2048,6144]
    gemm_bias_kernel<<<dim3(N1_ / 128, M_ / 128), 256>>>(x, Wqkv, bqkv, qkv,
                                                         M_, N1_, C_);

    // 2) causal flash attention -> att [8192,2048]
    const size_t fsmem = FLASH_SMEM_FLOATS * sizeof(float);  // ~113 KB
    cudaFuncSetAttribute(flash_kernel,
                         cudaFuncAttributeMaxDynamicSharedMemorySize,
                         (int)fsmem);
    flash_kernel<<<dim3(B_ * H_, T_ / BR), 256, fsmem>>>(qkv, att);

    // 3) out = att @ Wproj + bproj  [8192,2048]x[2048,2048]
    gemm_bias_kernel<<<dim3(C_ / 128, M_ / 128), 256>>>(att, Wproj, bproj, out,
                                                        M_, C_, C_);
}

// round 3
// speedup vs baseline: 1.7434x; 1.7434x over previous
#include <cuda_runtime.h>
#include <cuda_bf16.h>
#include <cstdint>
#include <cstddef>

// Problem constants (B=4, T=2048, C=2048, H=16, D=128)
#define B_  4
#define T_  2048
#define C_  2048
#define H_  16
#define D_  128
#define M_  (B_ * T_)       // 8192
#define N1_ (3 * C_)        // 6144

// ---------------------------------------------------------------------------
// Scratch (__device__ globals; no allocs allowed)
// ---------------------------------------------------------------------------
__device__ float g_qkv[(size_t)M_ * N1_];                 // 201 MB
__device__ float g_att[(size_t)M_ * C_];                  // 67 MB
__device__ __nv_bfloat16 g_xhi[(size_t)M_ * C_];
__device__ __nv_bfloat16 g_xlo[(size_t)M_ * C_];
__device__ __nv_bfloat16 g_w1hi[(size_t)N1_ * C_];        // Wqkv^T [6144,2048]
__device__ __nv_bfloat16 g_w1lo[(size_t)N1_ * C_];
__device__ __nv_bfloat16 g_w2hi[(size_t)C_ * C_];         // Wproj^T [2048,2048]
__device__ __nv_bfloat16 g_w2lo[(size_t)C_ * C_];
__device__ __nv_bfloat16 g_ahi[(size_t)M_ * C_];
__device__ __nv_bfloat16 g_alo[(size_t)M_ * C_];

// ---------------------------------------------------------------------------
// Helpers
// ---------------------------------------------------------------------------
__device__ __forceinline__ uint32_t smem_u32(const void* p) {
    uint32_t a;
    asm("{ .reg .u64 t; cvta.to.shared.u64 t, %1; cvt.u32.u64 %0, t; }"
        : "=r"(a) : "l"(p));
    return a;
}

#define LDSM_X4(r, a)                                                          \
    asm volatile("ldmatrix.sync.aligned.m8n8.x4.shared.b16 {%0,%1,%2,%3}, [%4];" \
        : "=r"((r)[0]), "=r"((r)[1]), "=r"((r)[2]), "=r"((r)[3]) : "r"(a))

#define LDSM_X2(r, a)                                                          \
    asm volatile("ldmatrix.sync.aligned.m8n8.x2.shared.b16 {%0,%1}, [%2];"     \
        : "=r"((r)[0]), "=r"((r)[1]) : "r"(a))

#define MMA16816(c, a, b)                                                      \
    asm volatile("mma.sync.aligned.m16n8k16.row.col.f32.bf16.bf16.f32 "        \
        "{%0,%1,%2,%3}, {%4,%5,%6,%7}, {%8,%9}, {%0,%1,%2,%3};"                \
        : "+f"((c)[0]), "+f"((c)[1]), "+f"((c)[2]), "+f"((c)[3])               \
        : "r"((a)[0]), "r"((a)[1]), "r"((a)[2]), "r"((a)[3]),                  \
          "r"((b)[0]), "r"((b)[1]))

#define CP_ASYNC16(dst, src)                                                   \
    asm volatile("cp.async.cg.shared.global [%0], [%1], 16;"                   \
        :: "r"(dst), "l"(src))
#define CP_COMMIT()  asm volatile("cp.async.commit_group;" ::: "memory")
#define CP_WAIT1()   asm volatile("cp.async.wait_group 1;" ::: "memory")
#define CP_WAIT0()   asm volatile("cp.async.wait_group 0;" ::: "memory")

// ---------------------------------------------------------------------------
// Split fp32 -> bf16 hi/lo (elementwise, float4-vectorized)
// ---------------------------------------------------------------------------
__global__ void split_kernel(const float* __restrict__ in,
                             __nv_bfloat16* __restrict__ hi,
                             __nv_bfloat16* __restrict__ lo, int n4)
{
    int i = blockIdx.x * blockDim.x + threadIdx.x;
    if (i >= n4) return;
    float4 v = ((const float4*)in)[i];
    __nv_bfloat16 h0 = __float2bfloat16_rn(v.x);
    __nv_bfloat16 h1 = __float2bfloat16_rn(v.y);
    __nv_bfloat16 h2 = __float2bfloat16_rn(v.z);
    __nv_bfloat16 h3 = __float2bfloat16_rn(v.w);
    __nv_bfloat16 l0 = __float2bfloat16_rn(v.x - __bfloat162float(h0));
    __nv_bfloat16 l1 = __float2bfloat16_rn(v.y - __bfloat162float(h1));
    __nv_bfloat16 l2 = __float2bfloat16_rn(v.z - __bfloat162float(h2));
    __nv_bfloat16 l3 = __float2bfloat16_rn(v.w - __bfloat162float(h3));
    __nv_bfloat162* H = (__nv_bfloat162*)hi;
    __nv_bfloat162* L = (__nv_bfloat162*)lo;
    H[2 * i]     = __halves2bfloat162(h0, h1);
    H[2 * i + 1] = __halves2bfloat162(h2, h3);
    L[2 * i]     = __halves2bfloat162(l0, l1);
    L[2 * i + 1] = __halves2bfloat162(l2, l3);
}

// ---------------------------------------------------------------------------
// Split + transpose: W[K,N] fp32 -> W^T hi/lo bf16 [N,K]
// ---------------------------------------------------------------------------
__global__ __launch_bounds__(256)
void split_transpose_kernel(const float* __restrict__ W,
                            __nv_bfloat16* __restrict__ hiT,
                            __nv_bfloat16* __restrict__ loT, int K, int N)
{
    __shared__ float t[32][33];
    const int n0 = blockIdx.x * 32, k0 = blockIdx.y * 32;
    const int tx = threadIdx.x, ty = threadIdx.y;
#pragma unroll
    for (int j = 0; j < 4; j++)
        t[ty + j * 8][tx] = W[(size_t)(k0 + ty + j * 8) * N + n0 + tx];
    __syncthreads();
#pragma unroll
    for (int j = 0; j < 4; j++) {
        float v = t[tx][ty + j * 8];
        __nv_bfloat16 h = __float2bfloat16_rn(v);
        __nv_bfloat16 l = __float2bfloat16_rn(v - __bfloat162float(h));
        size_t o = (size_t)(n0 + ty + j * 8) * K + k0 + tx;
        hiT[o] = h;
        loT[o] = l;
    }
}

// ---------------------------------------------------------------------------
// mma.sync split-bf16 GEMM: C[M,N] = A[M,K] @ B^T + bias
// A hi/lo bf16 [M,K]; B hi/lo bf16 [N,K] (pre-transposed). K-major both.
// CTA 128x128, K-chunk 64, 8 warps (2x4 grid, warp tile 64x32),
// cp.async double-buffered SMEM with XOR swizzle.
// ---------------------------------------------------------------------------
#define TILE_B 16384            // 128 rows x 128 bytes (64 bf16)
#define BUF_B  (4 * TILE_B)     // Ahi, Alo, Bhi, Blo
#define GEMM_SMEM (2 * BUF_B)   // 128 KB

__device__ __forceinline__ void load_chunk(uint32_t sb, int buf,
                                           const __nv_bfloat16* sA_hi,
                                           const __nv_bfloat16* sA_lo,
                                           const __nv_bfloat16* sB_hi,
                                           const __nv_bfloat16* sB_lo,
                                           int k0, int Kdim, int tid)
{
    const __nv_bfloat16* srcs[4] = { sA_hi, sA_lo, sB_hi, sB_lo };
    const uint32_t bufo = (uint32_t)buf * BUF_B;
#pragma unroll
    for (int tl = 0; tl < 4; tl++) {
        const __nv_bfloat16* s = srcs[tl] + k0;
        const uint32_t tb = sb + bufo + (uint32_t)tl * TILE_B;
#pragma unroll
        for (int l = 0; l < 4; l++) {
            int idx = tid + l * 256;
            int row = idx >> 3, seg = idx & 7;
            const void* g = s + (size_t)row * Kdim + seg * 8;
            uint32_t d = tb + (uint32_t)(row * 128 + ((seg * 16) ^ ((row & 7) << 4)));
            CP_ASYNC16(d, g);
        }
    }
    CP_COMMIT();
}

__global__ __launch_bounds__(256, 1)
void mma_gemm(const __nv_bfloat16* __restrict__ Ahi, const __nv_bfloat16* __restrict__ Alo,
              const __nv_bfloat16* __restrict__ Bhi, const __nv_bfloat16* __restrict__ Blo,
              const float* __restrict__ bias, float* __restrict__ Cm,
              int Mdim, int Ndim, int Kdim)
{
    extern __shared__ __align__(128) char smem[];
    const uint32_t sb = smem_u32(smem);
    const int tid  = threadIdx.x;
    const int wid  = tid >> 5;
    const int lane = tid & 31;
    const int wm   = wid & 1;        // 0..1  -> 64 rows
    const int wn   = wid >> 1;       // 0..3  -> 32 cols
    const int m0   = blockIdx.y * 128;
    const int n0   = blockIdx.x * 128;

    const __nv_bfloat16* aHi = Ahi + (size_t)m0 * Kdim;
    const __nv_bfloat16* aLo = Alo + (size_t)m0 * Kdim;
    const __nv_bfloat16* bHi = Bhi + (size_t)n0 * Kdim;
    const __nv_bfloat16* bLo = Blo + (size_t)n0 * Kdim;

    // Per-lane ldmatrix addressing (XOR swizzle: SW(row*128+kb) = row*128 + (kb ^ (row&7)<<4))
    const uint32_t aRowOff = (uint32_t)((wm * 64 + (lane & 15)) * 128);
    const uint32_t aKxor   = (uint32_t)((lane & 7) << 4);
    const uint32_t aKadd   = (uint32_t)((lane >> 4) * 16);
    const uint32_t bRowOff = (uint32_t)((wn * 32 + (lane & 7)) * 128);
    const uint32_t bKadd   = (uint32_t)(((lane >> 3) & 1) * 16);

    float c[4][4][4];
#pragma unroll
    for (int mi = 0; mi < 4; mi++)
#pragma unroll
        for (int ni = 0; ni < 4; ni++)
#pragma unroll
            for (int e = 0; e < 4; e++) c[mi][ni][e] = 0.f;

    const int nch = Kdim >> 6;       // K-chunks of 64
    load_chunk(sb, 0, aHi, aLo, bHi, bLo, 0, Kdim, tid);

    for (int t = 0; t < nch; t++) {
        if (t + 1 < nch) {
            load_chunk(sb, (t + 1) & 1, aHi, aLo, bHi, bLo, (t + 1) << 6, Kdim, tid);
            CP_WAIT1();
        } else {
            CP_WAIT0();
        }
        __syncthreads();

        const uint32_t bufo = sb + (uint32_t)(t & 1) * BUF_B;
        const uint32_t tAh = bufo;
        const uint32_t tAl = bufo + TILE_B;
        const uint32_t tBh = bufo + 2 * TILE_B;
        const uint32_t tBl = bufo + 3 * TILE_B;

#pragma unroll
        for (int ks = 0; ks < 4; ks++) {
            const uint32_t aK = ((uint32_t)(ks * 32) + aKadd) ^ aKxor;
            const uint32_t bK = ((uint32_t)(ks * 32) + bKadd) ^ aKxor;
            uint32_t ah[4][4], al[4][4], bh[4][2], bl[4][2];
#pragma unroll
            for (int mi = 0; mi < 4; mi++) {
                LDSM_X4(ah[mi], tAh + aRowOff + (uint32_t)(mi * 2048) + aK);
                LDSM_X4(al[mi], tAl + aRowOff + (uint32_t)(mi * 2048) + aK);
            }
#pragma unroll
            for (int ni = 0; ni < 4; ni++) {
                LDSM_X2(bh[ni], tBh + bRowOff + (uint32_t)(ni * 1024) + bK);
                LDSM_X2(bl[ni], tBl + bRowOff + (uint32_t)(ni * 1024) + bK);
            }
#pragma unroll
            for (int mi = 0; mi < 4; mi++)
#pragma unroll
                for (int ni = 0; ni < 4; ni++) {
                    MMA16816(c[mi][ni], ah[mi], bh[ni]);
                    MMA16816(c[mi][ni], ah[mi], bl[ni]);
                    MMA16816(c[mi][ni], al[mi], bh[ni]);
                }
        }
        __syncthreads();
    }

    // Epilogue
    const int lr = lane >> 2;            // 0..7
    const int lc = (lane & 3) * 2;
#pragma unroll
    for (int mi = 0; mi < 4; mi++) {
        const int r0 = m0 + wm * 64 + mi * 16 + lr;
#pragma unroll
        for (int ni = 0; ni < 4; ni++) {
            const int col = n0 + wn * 32 + ni * 8 + lc;
            const float b0 = bias[col], b1 = bias[col + 1];
            float2 v0, v1;
            v0.x = c[mi][ni][0] + b0; v0.y = c[mi][ni][1] + b1;
            v1.x = c[mi][ni][2] + b0; v1.y = c[mi][ni][3] + b1;
            *(float2*)&Cm[(size_t)r0 * Ndim + col]       = v0;
            *(float2*)&Cm[(size_t)(r0 + 8) * Ndim + col] = v1;
        }
    }
}

// ---------------------------------------------------------------------------
// Causal flash-attention (fp32 SIMT, unchanged)
// ---------------------------------------------------------------------------
#define BR 64
#define BC 64
#define FLASH_SMEM_FLOATS (128*64 + 128*64 + 64*128 + 64*65 + 3*64)

__global__ __launch_bounds__(256, 1)
void flash_kernel(const float* __restrict__ qkv, float* __restrict__ att)
{
    extern __shared__ __align__(16) float sm[];
    float* sQ = sm;
    float* sK = sQ + 128 * 64;
    float* sV = sK + 128 * 64;
    float* sP = sV + 64 * 128;
    float* sMx = sP + 64 * 65;
    float* sL  = sMx + 64;
    float* sCo = sL + 64;

    const int tid = threadIdx.x;
    const int tc  = tid & 15;
    const int tr  = tid >> 4;
    const int bh  = blockIdx.x;
    const int b   = bh >> 4;
    const int h   = bh & 15;
    const int i0  = (gridDim.y - 1 - blockIdx.y) * BR;

    const size_t RS = (size_t)N1_;
    const float scale = 0.08838834764831844055f;

    const float* qb  = qkv + (size_t)(b * T_ + i0) * RS + h * D_;
    const float* kb0 = qkv + (size_t)b * T_ * RS + C_ + h * D_;
    const float* vb0 = qkv + (size_t)b * T_ * RS + 2 * C_ + h * D_;

#pragma unroll
    for (int l = 0; l < 8; l++) {
        int f  = tid + l * 256;
        int r  = f >> 5;
        int dc = (f & 31) << 2;
        float4 v = *(const float4*)(qb + (size_t)r * RS + dc);
        sQ[(dc + 0) * BR + r] = v.x * scale;
        sQ[(dc + 1) * BR + r] = v.y * scale;
        sQ[(dc + 2) * BR + r] = v.z * scale;
        sQ[(dc + 3) * BR + r] = v.w * scale;
    }
    if (tid < BR) { sMx[tid] = -1e30f; sL[tid] = 0.f; }

    float o[4][8];
#pragma unroll
    for (int i = 0; i < 4; i++)
#pragma unroll
        for (int d = 0; d < 8; d++) o[i][d] = 0.f;

    const int ntiles = i0 / BC + 1;
    for (int jt = 0; jt < ntiles; jt++) {
        const int j0 = jt * BC;
        __syncthreads();

        const float* kb = kb0 + (size_t)j0 * RS;
        const float* vb = vb0 + (size_t)j0 * RS;
#pragma unroll
        for (int l = 0; l < 8; l++) {
            int f  = tid + l * 256;
            int r  = f >> 5;
            int dc = (f & 31) << 2;
            float4 v = *(const float4*)(kb + (size_t)r * RS + dc);
            sK[(dc + 0) * BC + r] = v.x;
            sK[(dc + 1) * BC + r] = v.y;
            sK[(dc + 2) * BC + r] = v.z;
            sK[(dc + 3) * BC + r] = v.w;
            float4 w = *(const float4*)(vb + (size_t)r * RS + dc);
            *(float4*)(sV + r * 128 + dc) = w;
        }
        __syncthreads();

        float s[4][4];
#pragma unroll
        for (int i = 0; i < 4; i++)
#pragma unroll
            for (int j = 0; j < 4; j++) s[i][j] = 0.f;
#pragma unroll 8
        for (int k = 0; k < D_; k++) {
            float a[4], cc[4];
            *(float4*)a  = *(const float4*)(sQ + k * BR + tr * 4);
            *(float4*)cc = *(const float4*)(sK + k * BC + tc * 4);
#pragma unroll
            for (int i = 0; i < 4; i++)
#pragma unroll
                for (int j = 0; j < 4; j++)
                    s[i][j] += a[i] * cc[j];
        }

        if (jt == ntiles - 1) {
#pragma unroll
            for (int i = 0; i < 4; i++)
#pragma unroll
                for (int j = 0; j < 4; j++)
                    if (j0 + tc * 4 + j > i0 + tr * 4 + i) s[i][j] = -1e30f;
        }

#pragma unroll
        for (int i = 0; i < 4; i++)
#pragma unroll
            for (int j = 0; j < 4; j++)
                sP[(tr * 4 + i) * 65 + tc * 4 + j] = s[i][j];
        __syncthreads();

        if (tid < BR) {
            const int r = tid;
            float mold = sMx[r];
            float mx = mold;
#pragma unroll 8
            for (int j = 0; j < BC; j++) mx = fmaxf(mx, sP[r * 65 + j]);
            float corr = __expf(mold - mx);
            float l = sL[r] * corr;
#pragma unroll 8
            for (int j = 0; j < BC; j++) {
                float e = __expf(sP[r * 65 + j] - mx);
                sP[r * 65 + j] = e;
                l += e;
            }
            sMx[r] = mx; sL[r] = l; sCo[r] = corr;
        }
        __syncthreads();

        float cr[4];
#pragma unroll
        for (int i = 0; i < 4; i++) cr[i] = sCo[tr * 4 + i];
#pragma unroll
        for (int i = 0; i < 4; i++)
#pragma unroll
            for (int d = 0; d < 8; d++) o[i][d] *= cr[i];

#pragma unroll 4
        for (int j = 0; j < BC; j++) {
            float p[4];
#pragma unroll
            for (int i = 0; i < 4; i++) p[i] = sP[(tr * 4 + i) * 65 + j];
            float v0[4], v1[4];
            *(float4*)v0 = *(const float4*)(sV + j * 128 + tc * 8);
            *(float4*)v1 = *(const float4*)(sV + j * 128 + tc * 8 + 4);
#pragma unroll
            for (int i = 0; i < 4; i++) {
#pragma unroll
                for (int d = 0; d < 4; d++) {
                    o[i][d]     += p[i] * v0[d];
                    o[i][4 + d] += p[i] * v1[d];
                }
            }
        }
    }

    float* ob = att + (size_t)(b * T_ + i0) * C_ + h * D_;
#pragma unroll
    for (int i = 0; i < 4; i++) {
        float inv = 1.f / sL[tr * 4 + i];
        float4 r0, r1;
        r0.x = o[i][0] * inv; r0.y = o[i][1] * inv;
        r0.z = o[i][2] * inv; r0.w = o[i][3] * inv;
        r1.x = o[i][4] * inv; r1.y = o[i][5] * inv;
        r1.z = o[i][6] * inv; r1.w = o[i][7] * inv;
        *(float4*)(ob + (size_t)(tr * 4 + i) * C_ + tc * 8)     = r0;
        *(float4*)(ob + (size_t)(tr * 4 + i) * C_ + tc * 8 + 4) = r1;
    }
}

// ---------------------------------------------------------------------------
// Launch
// ---------------------------------------------------------------------------
extern "C" void kernel_launch(void* const* d_in, const int* in_sizes, int n_in,
                              void* d_out, int out_size)
{
    const float* x     = (const float*)d_in[0];
    const float* Wqkv  = (const float*)d_in[1];
    const float* bqkv  = (const float*)d_in[2];
    const float* Wproj = (const float*)d_in[3];
    const float* bproj = (const float*)d_in[4];
    float* out = (float*)d_out;

    float *qkv, *att;
    __nv_bfloat16 *xhi, *xlo, *w1hi, *w1lo, *w2hi, *w2lo, *ahi, *alo;
    cudaGetSymbolAddress((void**)&qkv,  g_qkv);
    cudaGetSymbolAddress((void**)&att,  g_att);
    cudaGetSymbolAddress((void**)&xhi,  g_xhi);
    cudaGetSymbolAddress((void**)&xlo,  g_xlo);
    cudaGetSymbolAddress((void**)&w1hi, g_w1hi);
    cudaGetSymbolAddress((void**)&w1lo, g_w1lo);
    cudaGetSymbolAddress((void**)&w2hi, g_w2hi);
    cudaGetSymbolAddress((void**)&w2lo, g_w2lo);
    cudaGetSymbolAddress((void**)&ahi,  g_ahi);
    cudaGetSymbolAddress((void**)&alo,  g_alo);

    cudaFuncSetAttribute(mma_gemm, cudaFuncAttributeMaxDynamicSharedMemorySize,
                         GEMM_SMEM);
    const size_t fsmem = FLASH_SMEM_FLOATS * sizeof(float);
    cudaFuncSetAttribute(flash_kernel,
                         cudaFuncAttributeMaxDynamicSharedMemorySize, (int)fsmem);

    const int n4x = (M_ * C_) / 4;

    // Split x; transpose+split weights
    split_kernel<<<n4x / 256, 256>>>(x, xhi, xlo, n4x);
    split_transpose_kernel<<<dim3(N1_ / 32, C_ / 32), dim3(32, 8)>>>(Wqkv, w1hi, w1lo, C_, N1_);
    split_transpose_kernel<<<dim3(C_ / 32, C_ / 32), dim3(32, 8)>>>(Wproj, w2hi, w2lo, C_, C_);

    // 1) qkv = x @ Wqkv + bqkv
    mma_gemm<<<dim3(N1_ / 128, M_ / 128), 256, GEMM_SMEM>>>(
        xhi, xlo, w1hi, w1lo, bqkv, qkv, M_, N1_, C_);

    // 2) causal flash attention
    flash_kernel<<<dim3(B_ * H_, T_ / BR), 256, fsmem>>>(qkv, att);

    // 3) split att; out = att @ Wproj + bproj
    split_kernel<<<n4x / 256, 256>>>(att, ahi, alo, n4x);
    mma_gemm<<<dim3(C_ / 128, M_ / 128), 256, GEMM_SMEM>>>(
        ahi, alo, w2hi, w2lo, bproj, out, M_, C_, C_);
}

// round 4
// speedup vs baseline: 3.3342x; 1.9125x over previous
#include <cuda_runtime.h>
#include <cuda_bf16.h>
#include <cstdint>
#include <cstddef>

// Problem constants (B=4, T=2048, C=2048, H=16, D=128)
#define B_  4
#define T_  2048
#define C_  2048
#define H_  16
#define D_  128
#define M_  (B_ * T_)       // 8192
#define N1_ (3 * C_)        // 6144

// ---------------------------------------------------------------------------
// Scratch (__device__ globals; no allocs allowed)
// ---------------------------------------------------------------------------
__device__ float g_qkv[(size_t)M_ * N1_];                 // 201 MB
__device__ float g_att[(size_t)M_ * C_];                  // 67 MB
__device__ __nv_bfloat16 g_xhi[(size_t)M_ * C_];
__device__ __nv_bfloat16 g_xlo[(size_t)M_ * C_];
__device__ __nv_bfloat16 g_w1hi[(size_t)N1_ * C_];        // Wqkv^T [6144,2048]
__device__ __nv_bfloat16 g_w1lo[(size_t)N1_ * C_];
__device__ __nv_bfloat16 g_w2hi[(size_t)C_ * C_];         // Wproj^T [2048,2048]
__device__ __nv_bfloat16 g_w2lo[(size_t)C_ * C_];
__device__ __nv_bfloat16 g_ahi[(size_t)M_ * C_];
__device__ __nv_bfloat16 g_alo[(size_t)M_ * C_];

// ---------------------------------------------------------------------------
// Helpers
// ---------------------------------------------------------------------------
__device__ __forceinline__ uint32_t smem_u32(const void* p) {
    uint32_t a;
    asm("{ .reg .u64 t; cvta.to.shared.u64 t, %1; cvt.u32.u64 %0, t; }"
        : "=r"(a) : "l"(p));
    return a;
}

#define LDSM_X4(r, a)                                                          \
    asm volatile("ldmatrix.sync.aligned.m8n8.x4.shared.b16 {%0,%1,%2,%3}, [%4];" \
        : "=r"((r)[0]), "=r"((r)[1]), "=r"((r)[2]), "=r"((r)[3]) : "r"(a))

#define LDSM_X2(r, a)                                                          \
    asm volatile("ldmatrix.sync.aligned.m8n8.x2.shared.b16 {%0,%1}, [%2];"     \
        : "=r"((r)[0]), "=r"((r)[1]) : "r"(a))

#define LDSM_X2_T(r, a)                                                        \
    asm volatile("ldmatrix.sync.aligned.m8n8.x2.trans.shared.b16 {%0,%1}, [%2];" \
        : "=r"((r)[0]), "=r"((r)[1]) : "r"(a))

#define MMA16816(c, a, b)                                                      \
    asm volatile("mma.sync.aligned.m16n8k16.row.col.f32.bf16.bf16.f32 "        \
        "{%0,%1,%2,%3}, {%4,%5,%6,%7}, {%8,%9}, {%0,%1,%2,%3};"                \
        : "+f"((c)[0]), "+f"((c)[1]), "+f"((c)[2]), "+f"((c)[3])               \
        : "r"((a)[0]), "r"((a)[1]), "r"((a)[2]), "r"((a)[3]),                  \
          "r"((b)[0]), "r"((b)[1]))

#define CP_ASYNC16(dst, src)                                                   \
    asm volatile("cp.async.cg.shared.global [%0], [%1], 16;"                   \
        :: "r"(dst), "l"(src))
#define CP_COMMIT()  asm volatile("cp.async.commit_group;" ::: "memory")
#define CP_WAIT1()   asm volatile("cp.async.wait_group 1;" ::: "memory")
#define CP_WAIT0()   asm volatile("cp.async.wait_group 0;" ::: "memory")

__device__ __forceinline__ uint32_t pack_bf2(float a, float b) {
    __nv_bfloat162 t = __halves2bfloat162(__float2bfloat16_rn(a),
                                          __float2bfloat16_rn(b));
    return *(uint32_t*)&t;
}

// split float4 into hi/lo bf16x2 pairs
__device__ __forceinline__ void split4(float4 v, uint32_t& h0, uint32_t& h1,
                                       uint32_t& l0, uint32_t& l1) {
    __nv_bfloat16 ax = __float2bfloat16_rn(v.x);
    __nv_bfloat16 ay = __float2bfloat16_rn(v.y);
    __nv_bfloat16 az = __float2bfloat16_rn(v.z);
    __nv_bfloat16 aw = __float2bfloat16_rn(v.w);
    __nv_bfloat162 th0 = __halves2bfloat162(ax, ay);
    __nv_bfloat162 th1 = __halves2bfloat162(az, aw);
    h0 = *(uint32_t*)&th0;
    h1 = *(uint32_t*)&th1;
    l0 = pack_bf2(v.x - __bfloat162float(ax), v.y - __bfloat162float(ay));
    l1 = pack_bf2(v.z - __bfloat162float(az), v.w - __bfloat162float(aw));
}

// ---------------------------------------------------------------------------
// Split fp32 -> bf16 hi/lo (elementwise)
// ---------------------------------------------------------------------------
__global__ void split_kernel(const float* __restrict__ in,
                             __nv_bfloat16* __restrict__ hi,
                             __nv_bfloat16* __restrict__ lo, int n4)
{
    int i = blockIdx.x * blockDim.x + threadIdx.x;
    if (i >= n4) return;
    float4 v = ((const float4*)in)[i];
    uint32_t h0, h1, l0, l1;
    split4(v, h0, h1, l0, l1);
    uint32_t* H = (uint32_t*)hi;
    uint32_t* L = (uint32_t*)lo;
    H[2 * i] = h0; H[2 * i + 1] = h1;
    L[2 * i] = l0; L[2 * i + 1] = l1;
}

// ---------------------------------------------------------------------------
// Split + transpose: W[K,N] fp32 -> W^T hi/lo bf16 [N,K]
// ---------------------------------------------------------------------------
__global__ __launch_bounds__(256)
void split_transpose_kernel(const float* __restrict__ W,
                            __nv_bfloat16* __restrict__ hiT,
                            __nv_bfloat16* __restrict__ loT, int K, int N)
{
    __shared__ float t[32][33];
    const int n0 = blockIdx.x * 32, k0 = blockIdx.y * 32;
    const int tx = threadIdx.x, ty = threadIdx.y;
#pragma unroll
    for (int j = 0; j < 4; j++)
        t[ty + j * 8][tx] = W[(size_t)(k0 + ty + j * 8) * N + n0 + tx];
    __syncthreads();
#pragma unroll
    for (int j = 0; j < 4; j++) {
        float v = t[tx][ty + j * 8];
        __nv_bfloat16 h = __float2bfloat16_rn(v);
        __nv_bfloat16 l = __float2bfloat16_rn(v - __bfloat162float(h));
        size_t o = (size_t)(n0 + ty + j * 8) * K + k0 + tx;
        hiT[o] = h;
        loT[o] = l;
    }
}

// ---------------------------------------------------------------------------
// mma.sync split-bf16 GEMM (unchanged from round 3 — tensor 75%)
// ---------------------------------------------------------------------------
#define TILE_B 16384
#define BUF_B  (4 * TILE_B)
#define GEMM_SMEM (2 * BUF_B)

__device__ __forceinline__ void load_chunk(uint32_t sb, int buf,
                                           const __nv_bfloat16* sA_hi,
                                           const __nv_bfloat16* sA_lo,
                                           const __nv_bfloat16* sB_hi,
                                           const __nv_bfloat16* sB_lo,
                                           int k0, int Kdim, int tid)
{
    const __nv_bfloat16* srcs[4] = { sA_hi, sA_lo, sB_hi, sB_lo };
    const uint32_t bufo = (uint32_t)buf * BUF_B;
#pragma unroll
    for (int tl = 0; tl < 4; tl++) {
        const __nv_bfloat16* s = srcs[tl] + k0;
        const uint32_t tb = sb + bufo + (uint32_t)tl * TILE_B;
#pragma unroll
        for (int l = 0; l < 4; l++) {
            int idx = tid + l * 256;
            int row = idx >> 3, seg = idx & 7;
            const void* g = s + (size_t)row * Kdim + seg * 8;
            uint32_t d = tb + (uint32_t)(row * 128 + ((seg * 16) ^ ((row & 7) << 4)));
            CP_ASYNC16(d, g);
        }
    }
    CP_COMMIT();
}

__global__ __launch_bounds__(256, 1)
void mma_gemm(const __nv_bfloat16* __restrict__ Ahi, const __nv_bfloat16* __restrict__ Alo,
              const __nv_bfloat16* __restrict__ Bhi, const __nv_bfloat16* __restrict__ Blo,
              const float* __restrict__ bias, float* __restrict__ Cm,
              int Mdim, int Ndim, int Kdim)
{
    extern __shared__ __align__(128) char smem[];
    const uint32_t sb = smem_u32(smem);
    const int tid  = threadIdx.x;
    const int wid  = tid >> 5;
    const int lane = tid & 31;
    const int wm   = wid & 1;
    const int wn   = wid >> 1;
    const int m0   = blockIdx.y * 128;
    const int n0   = blockIdx.x * 128;

    const __nv_bfloat16* aHi = Ahi + (size_t)m0 * Kdim;
    const __nv_bfloat16* aLo = Alo + (size_t)m0 * Kdim;
    const __nv_bfloat16* bHi = Bhi + (size_t)n0 * Kdim;
    const __nv_bfloat16* bLo = Blo + (size_t)n0 * Kdim;

    const uint32_t aRowOff = (uint32_t)((wm * 64 + (lane & 15)) * 128);
    const uint32_t aKxor   = (uint32_t)((lane & 7) << 4);
    const uint32_t aKadd   = (uint32_t)((lane >> 4) * 16);
    const uint32_t bRowOff = (uint32_t)((wn * 32 + (lane & 7)) * 128);
    const uint32_t bKadd   = (uint32_t)(((lane >> 3) & 1) * 16);

    float c[4][4][4];
#pragma unroll
    for (int mi = 0; mi < 4; mi++)
#pragma unroll
        for (int ni = 0; ni < 4; ni++)
#pragma unroll
            for (int e = 0; e < 4; e++) c[mi][ni][e] = 0.f;

    const int nch = Kdim >> 6;
    load_chunk(sb, 0, aHi, aLo, bHi, bLo, 0, Kdim, tid);

    for (int t = 0; t < nch; t++) {
        if (t + 1 < nch) {
            load_chunk(sb, (t + 1) & 1, aHi, aLo, bHi, bLo, (t + 1) << 6, Kdim, tid);
            CP_WAIT1();
        } else {
            CP_WAIT0();
        }
        __syncthreads();

        const uint32_t bufo = sb + (uint32_t)(t & 1) * BUF_B;
        const uint32_t tAh = bufo;
        const uint32_t tAl = bufo + TILE_B;
        const uint32_t tBh = bufo + 2 * TILE_B;
        const uint32_t tBl = bufo + 3 * TILE_B;

#pragma unroll
        for (int ks = 0; ks < 4; ks++) {
            const uint32_t aK = ((uint32_t)(ks * 32) + aKadd) ^ aKxor;
            const uint32_t bK = ((uint32_t)(ks * 32) + bKadd) ^ aKxor;
            uint32_t ah[4][4], al[4][4], bh[4][2], bl[4][2];
#pragma unroll
            for (int mi = 0; mi < 4; mi++) {
                LDSM_X4(ah[mi], tAh + aRowOff + (uint32_t)(mi * 2048) + aK);
                LDSM_X4(al[mi], tAl + aRowOff + (uint32_t)(mi * 2048) + aK);
            }
#pragma unroll
            for (int ni = 0; ni < 4; ni++) {
                LDSM_X2(bh[ni], tBh + bRowOff + (uint32_t)(ni * 1024) + bK);
                LDSM_X2(bl[ni], tBl + bRowOff + (uint32_t)(ni * 1024) + bK);
            }
#pragma unroll
            for (int mi = 0; mi < 4; mi++)
#pragma unroll
                for (int ni = 0; ni < 4; ni++) {
                    MMA16816(c[mi][ni], ah[mi], bh[ni]);
                    MMA16816(c[mi][ni], ah[mi], bl[ni]);
                    MMA16816(c[mi][ni], al[mi], bh[ni]);
                }
        }
        __syncthreads();
    }

    const int lr = lane >> 2;
    const int lc = (lane & 3) * 2;
#pragma unroll
    for (int mi = 0; mi < 4; mi++) {
        const int r0 = m0 + wm * 64 + mi * 16 + lr;
#pragma unroll
        for (int ni = 0; ni < 4; ni++) {
            const int col = n0 + wn * 32 + ni * 8 + lc;
            const float b0 = bias[col], b1 = bias[col + 1];
            float2 v0, v1;
            v0.x = c[mi][ni][0] + b0; v0.y = c[mi][ni][1] + b1;
            v1.x = c[mi][ni][2] + b0; v1.y = c[mi][ni][3] + b1;
            *(float2*)&Cm[(size_t)r0 * Ndim + col]       = v0;
            *(float2*)&Cm[(size_t)(r0 + 8) * Ndim + col] = v1;
        }
    }
}

// ---------------------------------------------------------------------------
// Flash attention on mma.sync (split-bf16, causal, online softmax)
// BR=128 q-rows/CTA, BC=64 kv-cols/tile, 8 warps.
// smem byte offsets:
//   Qhi 0..32K, Qlo 32K..64K           (128x128 bf16, 256B swizzled rows)
//   Khi 64K..80K, Klo 80K..96K         (64x128 bf16, 256B swizzled rows)
//   Vhi 96K..112K, Vlo 112K..128K     (64x128 bf16, 256B swizzled rows)
//   Phi 128K..144K, Plo 144K..160K    (128x64 bf16, 128B swizzled rows)
//   S   160K.. (128x66 f32 = 33792B)
//   stats (3x128 f32)
// ---------------------------------------------------------------------------
#define QHI_O 0u
#define QLO_O 32768u
#define KHI_O 65536u
#define KLO_O 81920u
#define VHI_O 98304u
#define VLO_O 114688u
#define PHI_O 131072u
#define PLO_O 147456u
#define SS_O  163840u
#define STAT_O 197632u
#define FL_SMEM 199168

__global__ __launch_bounds__(256, 1)
void flash_mma(const float* __restrict__ qkv, float* __restrict__ att)
{
    extern __shared__ __align__(1024) char smf[];
    const uint32_t sb = smem_u32(smf);
    float* sS  = (float*)(smf + SS_O);
    float* sMx = (float*)(smf + STAT_O);
    float* sL  = sMx + 128;
    float* sCo = sL + 128;

    const int tid  = threadIdx.x;
    const int wid  = tid >> 5, lane = tid & 31;
    const int wr   = wid >> 1, wc = wid & 1;
    const int b    = blockIdx.x >> 4, h = blockIdx.x & 15;
    const int i0   = ((int)gridDim.y - 1 - (int)blockIdx.y) * 128;
    const size_t RS = (size_t)N1_;
    // 1/sqrt(128) * log2(e): softmax done in base-2 (exp2f = single MUFU)
    const float SC = 0.08838834764831844f * 1.44269504088896340736f;

    const float* qb  = qkv + (size_t)(b * T_ + i0) * RS + h * D_;
    const float* kb0 = qkv + (size_t)b * T_ * RS + C_ + h * D_;
    const float* vb0 = qkv + (size_t)b * T_ * RS + 2 * C_ + h * D_;

    // ---- load Q (128x128 f32 -> scaled hi/lo bf16, swizzled) ----
#pragma unroll
    for (int l = 0; l < 16; l++) {
        int idx = tid + l * 256;
        int row = idx >> 5;
        int c   = (idx & 31) << 2;
        float4 v = *(const float4*)(qb + (size_t)row * RS + c);
        v.x *= SC; v.y *= SC; v.z *= SC; v.w *= SC;
        uint32_t h0, h1, l0, l1;
        split4(v, h0, h1, l0, l1);
        uint32_t off = (uint32_t)(row * 256) +
                       (((uint32_t)(c * 2)) ^ ((uint32_t)(row & 7) << 4));
        *(uint2*)(smf + QHI_O + off) = make_uint2(h0, h1);
        *(uint2*)(smf + QLO_O + off) = make_uint2(l0, l1);
    }
    if (tid < 128) { sMx[tid] = -1e30f; sL[tid] = 0.f; }

    float o[2][8][4];
#pragma unroll
    for (int mi = 0; mi < 2; mi++)
#pragma unroll
        for (int ni = 0; ni < 8; ni++)
#pragma unroll
            for (int e = 0; e < 4; e++) o[mi][ni][e] = 0.f;

    const uint32_t kxor  = (uint32_t)((lane & 7) << 4);
    const uint32_t aKadd = (uint32_t)((lane >> 4) << 4);
    const uint32_t bKadd = (uint32_t)(((lane >> 3) & 1) << 4);
    const uint32_t qRow  = (uint32_t)((wr * 32 + (lane & 15)) * 256);
    const uint32_t kRow  = (uint32_t)((wc * 32 + (lane & 7)) * 256);
    const uint32_t pRow  = (uint32_t)((wr * 32 + (lane & 15)) * 128);

    const int ntiles = i0 / 64 + 2;
    for (int jt = 0; jt < ntiles; jt++) {
        const int j0 = jt * 64;
        __syncthreads();
        // ---- load K/V tile (64x128 f32 -> hi/lo bf16, swizzled) ----
#pragma unroll
        for (int l = 0; l < 8; l++) {
            int idx = tid + l * 256;
            int row = idx >> 5;
            int c   = (idx & 31) << 2;
            uint32_t off = (uint32_t)(row * 256) +
                           (((uint32_t)(c * 2)) ^ ((uint32_t)(row & 7) << 4));
            float4 v = *(const float4*)(kb0 + (size_t)(j0 + row) * RS + c);
            uint32_t h0, h1, l0, l1;
            split4(v, h0, h1, l0, l1);
            *(uint2*)(smf + KHI_O + off) = make_uint2(h0, h1);
            *(uint2*)(smf + KLO_O + off) = make_uint2(l0, l1);
            float4 w = *(const float4*)(vb0 + (size_t)(j0 + row) * RS + c);
            split4(w, h0, h1, l0, l1);
            *(uint2*)(smf + VHI_O + off) = make_uint2(h0, h1);
            *(uint2*)(smf + VLO_O + off) = make_uint2(l0, l1);
        }
        __syncthreads();

        // ---- S = Qs @ K^T (split bf16: hh + hl + lh), 128x64 ----
        float s[2][4][4];
#pragma unroll
        for (int mi = 0; mi < 2; mi++)
#pragma unroll
            for (int ni = 0; ni < 4; ni++)
#pragma unroll
                for (int e = 0; e < 4; e++) s[mi][ni][e] = 0.f;

#pragma unroll
        for (int ks = 0; ks < 8; ks++) {
            const uint32_t ak = ((uint32_t)(ks * 32) + aKadd) ^ kxor;
            const uint32_t bk = ((uint32_t)(ks * 32) + bKadd) ^ kxor;
            uint32_t qh[2][4], ql[2][4], kh[4][2], kl[4][2];
#pragma unroll
            for (int mi = 0; mi < 2; mi++) {
                LDSM_X4(qh[mi], sb + QHI_O + qRow + (uint32_t)(mi * 4096) + ak);
                LDSM_X4(ql[mi], sb + QLO_O + qRow + (uint32_t)(mi * 4096) + ak);
            }
#pragma unroll
            for (int ni = 0; ni < 4; ni++) {
                LDSM_X2(kh[ni], sb + KHI_O + kRow + (uint32_t)(ni * 2048) + bk);
                LDSM_X2(kl[ni], sb + KLO_O + kRow + (uint32_t)(ni * 2048) + bk);
            }
#pragma unroll
            for (int mi = 0; mi < 2; mi++)
#pragma unroll
                for (int ni = 0; ni < 4; ni++) {
                    MMA16816(s[mi][ni], qh[mi], kh[ni]);
                    MMA16816(s[mi][ni], qh[mi], kl[ni]);
                    MMA16816(s[mi][ni], ql[mi], kh[ni]);
                }
        }

        // ---- causal mask (only near the diagonal) ----
        if (jt >= ntiles - 2) {
            const int rbase = i0 + wr * 32 + (lane >> 2);
            const int cbase = j0 + wc * 32 + ((lane & 3) << 1);
#pragma unroll
            for (int mi = 0; mi < 2; mi++)
#pragma unroll
                for (int ni = 0; ni < 4; ni++) {
                    int rr = rbase + mi * 16;
                    int cc = cbase + ni * 8;
                    if (cc     > rr)     s[mi][ni][0] = -1e30f;
                    if (cc + 1 > rr)     s[mi][ni][1] = -1e30f;
                    if (cc     > rr + 8) s[mi][ni][2] = -1e30f;
                    if (cc + 1 > rr + 8) s[mi][ni][3] = -1e30f;
                }
        }

        // ---- store S frags to smem ----
        {
            const int r  = wr * 32 + (lane >> 2);
            const int cc = wc * 32 + ((lane & 3) << 1);
#pragma unroll
            for (int mi = 0; mi < 2; mi++)
#pragma unroll
                for (int ni = 0; ni < 4; ni++) {
                    float2 a; a.x = s[mi][ni][0]; a.y = s[mi][ni][1];
                    float2 d; d.x = s[mi][ni][2]; d.y = s[mi][ni][3];
                    *(float2*)&sS[(r + mi * 16) * 66 + cc + ni * 8]     = a;
                    *(float2*)&sS[(r + mi * 16 + 8) * 66 + cc + ni * 8] = d;
                }
        }
        __syncthreads();

        // ---- online softmax (2 threads per row, 32 cols each) ----
        {
            const int r  = tid >> 1;
            const int hh = tid & 1;
            const float* rowp = sS + r * 66 + hh * 32;
            float m = rowp[0];
#pragma unroll 8
            for (int j = 1; j < 32; j++) m = fmaxf(m, rowp[j]);
            m = fmaxf(m, __shfl_xor_sync(0xffffffffu, m, 1));
            const float mold = sMx[r];
            const float mx   = fmaxf(mold, m);
            const float corr = exp2f(mold - mx);
            float sum = 0.f;
            const uint32_t pb = (uint32_t)(r * 128);
            const uint32_t rx = (uint32_t)((r & 7) << 4);
#pragma unroll 4
            for (int jj = 0; jj < 16; jj++) {
                float e0 = exp2f(rowp[2 * jj]     - mx);
                float e1 = exp2f(rowp[2 * jj + 1] - mx);
                sum += e0 + e1;
                __nv_bfloat16 b0 = __float2bfloat16_rn(e0);
                __nv_bfloat16 b1 = __float2bfloat16_rn(e1);
                __nv_bfloat162 hp = __halves2bfloat162(b0, b1);
                uint32_t lp = pack_bf2(e0 - __bfloat162float(b0),
                                       e1 - __bfloat162float(b1));
                uint32_t off = pb + (((uint32_t)(hh * 64 + jj * 4)) ^ rx);
                *(uint32_t*)(smf + PHI_O + off) = *(uint32_t*)&hp;
                *(uint32_t*)(smf + PLO_O + off) = lp;
            }
            sum += __shfl_xor_sync(0xffffffffu, sum, 1);
            if (hh == 0) {
                sMx[r] = mx;
                sL[r]  = sL[r] * corr + sum;
                sCo[r] = corr;
            }
        }
        __syncthreads();

        // ---- rescale O, then O += P @ V (split bf16, ldmatrix.trans for V) ----
        {
            float c0[2], c1[2];
#pragma unroll
            for (int mi = 0; mi < 2; mi++) {
                c0[mi] = sCo[wr * 32 + mi * 16 + (lane >> 2)];
                c1[mi] = sCo[wr * 32 + mi * 16 + (lane >> 2) + 8];
            }
#pragma unroll
            for (int mi = 0; mi < 2; mi++)
#pragma unroll
                for (int ni = 0; ni < 8; ni++) {
                    o[mi][ni][0] *= c0[mi]; o[mi][ni][1] *= c0[mi];
                    o[mi][ni][2] *= c1[mi]; o[mi][ni][3] *= c1[mi];
                }
        }
#pragma unroll
        for (int ks = 0; ks < 4; ks++) {
            const uint32_t pk = ((uint32_t)(ks * 32) + aKadd) ^ kxor;
            const int vrow = ks * 16 + (lane & 15);
            const uint32_t vb = (uint32_t)(vrow * 256);
            const uint32_t vx = (uint32_t)((vrow & 7) << 4);
            uint32_t ph[2][4], pl[2][4], vh[8][2], vl[8][2];
#pragma unroll
            for (int mi = 0; mi < 2; mi++) {
                LDSM_X4(ph[mi], sb + PHI_O + pRow + (uint32_t)(mi * 2048) + pk);
                LDSM_X4(pl[mi], sb + PLO_O + pRow + (uint32_t)(mi * 2048) + pk);
            }
#pragma unroll
            for (int ni = 0; ni < 8; ni++) {
                const uint32_t cbo = ((uint32_t)(wc * 128 + ni * 16)) ^ vx;
                LDSM_X2_T(vh[ni], sb + VHI_O + vb + cbo);
                LDSM_X2_T(vl[ni], sb + VLO_O + vb + cbo);
            }
#pragma unroll
            for (int mi = 0; mi < 2; mi++)
#pragma unroll
                for (int ni = 0; ni < 8; ni++) {
                    MMA16816(o[mi][ni], ph[mi], vh[ni]);
                    MMA16816(o[mi][ni], ph[mi], vl[ni]);
                    MMA16816(o[mi][ni], pl[mi], vh[ni]);
                }
        }
    }

    // ---- epilogue: normalize by 1/L, store ----
    {
        const int r0 = wr * 32 + (lane >> 2);
        const int cc = wc * 64 + ((lane & 3) << 1);
#pragma unroll
        for (int mi = 0; mi < 2; mi++) {
            const int ra = r0 + mi * 16;
            const float ia = 1.f / sL[ra];
            const float ib = 1.f / sL[ra + 8];
            float* oa = att + (size_t)(b * T_ + i0 + ra) * C_ + h * D_;
            float* ob = att + (size_t)(b * T_ + i0 + ra + 8) * C_ + h * D_;
#pragma unroll
            for (int ni = 0; ni < 8; ni++) {
                float2 v0, v1;
                v0.x = o[mi][ni][0] * ia; v0.y = o[mi][ni][1] * ia;
                v1.x = o[mi][ni][2] * ib; v1.y = o[mi][ni][3] * ib;
                *(float2*)(oa + cc + ni * 8) = v0;
                *(float2*)(ob + cc + ni * 8) = v1;
            }
        }
    }
}

// ---------------------------------------------------------------------------
// Launch
// ---------------------------------------------------------------------------
extern "C" void kernel_launch(void* const* d_in, const int* in_sizes, int n_in,
                              void* d_out, int out_size)
{
    const float* x     = (const float*)d_in[0];
    const float* Wqkv  = (const float*)d_in[1];
    const float* bqkv  = (const float*)d_in[2];
    const float* Wproj = (const float*)d_in[3];
    const float* bproj = (const float*)d_in[4];
    float* out = (float*)d_out;

    float *qkv, *att;
    __nv_bfloat16 *xhi, *xlo, *w1hi, *w1lo, *w2hi, *w2lo, *ahi, *alo;
    cudaGetSymbolAddress((void**)&qkv,  g_qkv);
    cudaGetSymbolAddress((void**)&att,  g_att);
    cudaGetSymbolAddress((void**)&xhi,  g_xhi);
    cudaGetSymbolAddress((void**)&xlo,  g_xlo);
    cudaGetSymbolAddress((void**)&w1hi, g_w1hi);
    cudaGetSymbolAddress((void**)&w1lo, g_w1lo);
    cudaGetSymbolAddress((void**)&w2hi, g_w2hi);
    cudaGetSymbolAddress((void**)&w2lo, g_w2lo);
    cudaGetSymbolAddress((void**)&ahi,  g_ahi);
    cudaGetSymbolAddress((void**)&alo,  g_alo);

    cudaFuncSetAttribute(mma_gemm, cudaFuncAttributeMaxDynamicSharedMemorySize,
                         GEMM_SMEM);
    cudaFuncSetAttribute(flash_mma, cudaFuncAttributeMaxDynamicSharedMemorySize,
                         FL_SMEM);

    const int n4x = (M_ * C_) / 4;

    // Split x; transpose+split weights
    split_kernel<<<n4x / 256, 256>>>(x, xhi, xlo, n4x);
    split_transpose_kernel<<<dim3(N1_ / 32, C_ / 32), dim3(32, 8)>>>(Wqkv, w1hi, w1lo, C_, N1_);
    split_transpose_kernel<<<dim3(C_ / 32, C_ / 32), dim3(32, 8)>>>(Wproj, w2hi, w2lo, C_, C_);

    // 1) qkv = x @ Wqkv + bqkv
    mma_gemm<<<dim3(N1_ / 128, M_ / 128), 256, GEMM_SMEM>>>(
        xhi, xlo, w1hi, w1lo, bqkv, qkv, M_, N1_, C_);

    // 2) causal flash attention (mma.sync)
    flash_mma<<<dim3(B_ * H_, T_ / 128), 256, FL_SMEM>>>(qkv, att);

    // 3) split att; out = att @ Wproj + bproj
    split_kernel<<<n4x / 256, 256>>>(att, ahi, alo, n4x);
    mma_gemm<<<dim3(C_ / 128, M_ / 128), 256, GEMM_SMEM>>>(
        ahi, alo, w2hi, w2lo, bproj, out, M_, C_, C_);
}

// round 5
// speedup vs baseline: 3.5469x; 1.0638x over previous
#include <cuda_runtime.h>
#include <cuda_bf16.h>
#include <cstdint>
#include <cstddef>

// Problem constants (B=4, T=2048, C=2048, H=16, D=128)
#define B_  4
#define T_  2048
#define C_  2048
#define H_  16
#define D_  128
#define M_  (B_ * T_)       // 8192
#define N1_ (3 * C_)        // 6144

// ---------------------------------------------------------------------------
// Scratch (__device__ globals; no allocs allowed)
// ---------------------------------------------------------------------------
__device__ float g_qkv[(size_t)M_ * N1_];
__device__ float g_att[(size_t)M_ * C_];
__device__ __nv_bfloat16 g_xhi[(size_t)M_ * C_];
__device__ __nv_bfloat16 g_xlo[(size_t)M_ * C_];
__device__ __nv_bfloat16 g_w1hi[(size_t)N1_ * C_];
__device__ __nv_bfloat16 g_w1lo[(size_t)N1_ * C_];
__device__ __nv_bfloat16 g_w2hi[(size_t)C_ * C_];
__device__ __nv_bfloat16 g_w2lo[(size_t)C_ * C_];
__device__ __nv_bfloat16 g_ahi[(size_t)M_ * C_];
__device__ __nv_bfloat16 g_alo[(size_t)M_ * C_];

// ---------------------------------------------------------------------------
// Helpers
// ---------------------------------------------------------------------------
__device__ __forceinline__ uint32_t smem_u32(const void* p) {
    uint32_t a;
    asm("{ .reg .u64 t; cvta.to.shared.u64 t, %1; cvt.u32.u64 %0, t; }"
        : "=r"(a) : "l"(p));
    return a;
}

#define LDSM_X4(r, a)                                                          \
    asm volatile("ldmatrix.sync.aligned.m8n8.x4.shared.b16 {%0,%1,%2,%3}, [%4];" \
        : "=r"((r)[0]), "=r"((r)[1]), "=r"((r)[2]), "=r"((r)[3]) : "r"(a))

#define LDSM_X4_T(r, a)                                                        \
    asm volatile("ldmatrix.sync.aligned.m8n8.x4.trans.shared.b16 {%0,%1,%2,%3}, [%2_DUMMY];" \
        : "=r"((r)[0]) : )
#undef LDSM_X4_T
#define LDSM_X4_T(r, a)                                                        \
    asm volatile("ldmatrix.sync.aligned.m8n8.x4.trans.shared.b16 {%0,%1,%2,%3}, [%4];" \
        : "=r"((r)[0]), "=r"((r)[1]), "=r"((r)[2]), "=r"((r)[3]) : "r"(a))

#define MMA16816(c, a, b0v, b1v)                                               \
    asm volatile("mma.sync.aligned.m16n8k16.row.col.f32.bf16.bf16.f32 "        \
        "{%0,%1,%2,%3}, {%4,%5,%6,%7}, {%8,%9}, {%0,%1,%2,%3};"                \
        : "+f"((c)[0]), "+f"((c)[1]), "+f"((c)[2]), "+f"((c)[3])               \
        : "r"((a)[0]), "r"((a)[1]), "r"((a)[2]), "r"((a)[3]),                  \
          "r"(b0v), "r"(b1v))

#define CP_ASYNC16(dst, src)                                                   \
    asm volatile("cp.async.cg.shared.global [%0], [%1], 16;"                   \
        :: "r"(dst), "l"(src))
#define CP_COMMIT()  asm volatile("cp.async.commit_group;" ::: "memory")
#define CP_WAIT1()   asm volatile("cp.async.wait_group 1;" ::: "memory")
#define CP_WAIT0()   asm volatile("cp.async.wait_group 0;" ::: "memory")

__device__ __forceinline__ uint32_t pack_bf2(float a, float b) {
    __nv_bfloat162 t = __halves2bfloat162(__float2bfloat16_rn(a),
                                          __float2bfloat16_rn(b));
    return *(uint32_t*)&t;
}

__device__ __forceinline__ void split4(float4 v, uint32_t& h0, uint32_t& h1,
                                       uint32_t& l0, uint32_t& l1) {
    __nv_bfloat16 ax = __float2bfloat16_rn(v.x);
    __nv_bfloat16 ay = __float2bfloat16_rn(v.y);
    __nv_bfloat16 az = __float2bfloat16_rn(v.z);
    __nv_bfloat16 aw = __float2bfloat16_rn(v.w);
    __nv_bfloat162 th0 = __halves2bfloat162(ax, ay);
    __nv_bfloat162 th1 = __halves2bfloat162(az, aw);
    h0 = *(uint32_t*)&th0;
    h1 = *(uint32_t*)&th1;
    l0 = pack_bf2(v.x - __bfloat162float(ax), v.y - __bfloat162float(ay));
    l1 = pack_bf2(v.z - __bfloat162float(az), v.w - __bfloat162float(aw));
}

// ---------------------------------------------------------------------------
// Split fp32 -> bf16 hi/lo
// ---------------------------------------------------------------------------
__global__ void split_kernel(const float* __restrict__ in,
                             __nv_bfloat16* __restrict__ hi,
                             __nv_bfloat16* __restrict__ lo, int n4)
{
    int i = blockIdx.x * blockDim.x + threadIdx.x;
    if (i >= n4) return;
    float4 v = ((const float4*)in)[i];
    uint32_t h0, h1, l0, l1;
    split4(v, h0, h1, l0, l1);
    uint32_t* H = (uint32_t*)hi;
    uint32_t* L = (uint32_t*)lo;
    H[2 * i] = h0; H[2 * i + 1] = h1;
    L[2 * i] = l0; L[2 * i + 1] = l1;
}

// ---------------------------------------------------------------------------
// Split + transpose: W[K,N] fp32 -> W^T hi/lo bf16 [N,K]
// ---------------------------------------------------------------------------
__global__ __launch_bounds__(256)
void split_transpose_kernel(const float* __restrict__ W,
                            __nv_bfloat16* __restrict__ hiT,
                            __nv_bfloat16* __restrict__ loT, int K, int N)
{
    __shared__ float t[32][33];
    const int n0 = blockIdx.x * 32, k0 = blockIdx.y * 32;
    const int tx = threadIdx.x, ty = threadIdx.y;
#pragma unroll
    for (int j = 0; j < 4; j++)
        t[ty + j * 8][tx] = W[(size_t)(k0 + ty + j * 8) * N + n0 + tx];
    __syncthreads();
#pragma unroll
    for (int j = 0; j < 4; j++) {
        float v = t[tx][ty + j * 8];
        __nv_bfloat16 h = __float2bfloat16_rn(v);
        __nv_bfloat16 l = __float2bfloat16_rn(v - __bfloat162float(h));
        size_t o = (size_t)(n0 + ty + j * 8) * K + k0 + tx;
        hiT[o] = h;
        loT[o] = l;
    }
}

// ---------------------------------------------------------------------------
// mma.sync split-bf16 GEMM: 128x256 CTA tile, 8 warps of 64x64, K-chunk 64.
// Double-buffered cp.async; SW-XOR swizzled 128B rows.
// Stage layout: Ahi 16K | Alo 16K | Bhi 32K | Blo 32K = 96K; 2 stages = 192K.
// ---------------------------------------------------------------------------
#define G_STAGE 98304u
#define GEMM_SMEM (2 * 98304)

__device__ __forceinline__ void load_chunk2(uint32_t sb, int buf,
                                            const __nv_bfloat16* aHi,
                                            const __nv_bfloat16* aLo,
                                            const __nv_bfloat16* bHi,
                                            const __nv_bfloat16* bLo,
                                            int k0, int Kdim, int tid)
{
    const uint32_t st = sb + (uint32_t)buf * G_STAGE;
    // A tiles: 128 rows x 128B  (1024 16B slots each)
    {
        const __nv_bfloat16* srcs[2] = { aHi, aLo };
#pragma unroll
        for (int tl = 0; tl < 2; tl++) {
            const __nv_bfloat16* s = srcs[tl] + k0;
            const uint32_t tb = st + (uint32_t)tl * 16384u;
#pragma unroll
            for (int l = 0; l < 4; l++) {
                int idx = tid + l * 256;
                int row = idx >> 3, seg = idx & 7;
                CP_ASYNC16(tb + (uint32_t)(row * 128 + ((seg * 16) ^ ((row & 7) << 4))),
                           s + (size_t)row * Kdim + seg * 8);
            }
        }
    }
    // B tiles: 256 rows x 128B  (2048 slots each)
    {
        const __nv_bfloat16* srcs[2] = { bHi, bLo };
#pragma unroll
        for (int tl = 0; tl < 2; tl++) {
            const __nv_bfloat16* s = srcs[tl] + k0;
            const uint32_t tb = st + 32768u + (uint32_t)tl * 32768u;
#pragma unroll
            for (int l = 0; l < 8; l++) {
                int idx = tid + l * 256;
                int row = idx >> 3, seg = idx & 7;
                CP_ASYNC16(tb + (uint32_t)(row * 128 + ((seg * 16) ^ ((row & 7) << 4))),
                           s + (size_t)row * Kdim + seg * 8);
            }
        }
    }
    CP_COMMIT();
}

__global__ __launch_bounds__(256, 1)
void mma_gemm(const __nv_bfloat16* __restrict__ Ahi, const __nv_bfloat16* __restrict__ Alo,
              const __nv_bfloat16* __restrict__ Bhi, const __nv_bfloat16* __restrict__ Blo,
              const float* __restrict__ bias, float* __restrict__ Cm,
              int Mdim, int Ndim, int Kdim)
{
    extern __shared__ __align__(128) char smem[];
    const uint32_t sb = smem_u32(smem);
    const int tid  = threadIdx.x;
    const int wid  = tid >> 5;
    const int lane = tid & 31;
    const int wm   = wid & 1;        // 0..1 -> 64 rows
    const int wn   = wid >> 1;       // 0..3 -> 64 cols
    const int m0   = blockIdx.y * 128;
    const int n0   = blockIdx.x * 256;

    const __nv_bfloat16* aHi = Ahi + (size_t)m0 * Kdim;
    const __nv_bfloat16* aLo = Alo + (size_t)m0 * Kdim;
    const __nv_bfloat16* bHi = Bhi + (size_t)n0 * Kdim;
    const __nv_bfloat16* bLo = Blo + (size_t)n0 * Kdim;

    const uint32_t kxor    = (uint32_t)((lane & 7) << 4);
    const uint32_t aRowOff = (uint32_t)((wm * 64 + (lane & 15)) * 128);
    const uint32_t aKadd   = (uint32_t)((lane >> 4) * 16);
    // B x4: row = wn*64 + pr*16 + ((lane>>4)&1)*8 + (lane&7); (row&7)==(lane&7)
    const uint32_t bRowOff = (uint32_t)((wn * 64 + ((lane >> 4) & 1) * 8 + (lane & 7)) * 128);
    const uint32_t bKadd   = (uint32_t)(((lane >> 3) & 1) * 16);

    float c[4][8][4];
#pragma unroll
    for (int mi = 0; mi < 4; mi++)
#pragma unroll
        for (int ni = 0; ni < 8; ni++)
#pragma unroll
            for (int e = 0; e < 4; e++) c[mi][ni][e] = 0.f;

    const int nch = Kdim >> 6;
    load_chunk2(sb, 0, aHi, aLo, bHi, bLo, 0, Kdim, tid);

    for (int t = 0; t < nch; t++) {
        if (t + 1 < nch) {
            load_chunk2(sb, (t + 1) & 1, aHi, aLo, bHi, bLo, (t + 1) << 6, Kdim, tid);
            CP_WAIT1();
        } else {
            CP_WAIT0();
        }
        __syncthreads();

        const uint32_t st  = sb + (uint32_t)(t & 1) * G_STAGE;
        const uint32_t tAh = st;
        const uint32_t tAl = st + 16384u;
        const uint32_t tBh = st + 32768u;
        const uint32_t tBl = st + 65536u;

#pragma unroll
        for (int ks = 0; ks < 4; ks++) {
            const uint32_t aK = ((uint32_t)(ks * 32) + aKadd) ^ kxor;
            const uint32_t bK = ((uint32_t)(ks * 32) + bKadd) ^ kxor;
            uint32_t ah[4][4], al[4][4];
#pragma unroll
            for (int mi = 0; mi < 4; mi++) {
                LDSM_X4(ah[mi], tAh + aRowOff + (uint32_t)(mi * 2048) + aK);
                LDSM_X4(al[mi], tAl + aRowOff + (uint32_t)(mi * 2048) + aK);
            }
#pragma unroll
            for (int pr = 0; pr < 4; pr++) {
                uint32_t bh4[4], bl4[4];
                LDSM_X4(bh4, tBh + bRowOff + (uint32_t)(pr * 2048) + bK);
                LDSM_X4(bl4, tBl + bRowOff + (uint32_t)(pr * 2048) + bK);
#pragma unroll
                for (int mi = 0; mi < 4; mi++) {
                    MMA16816(c[mi][2 * pr],     ah[mi], bh4[0], bh4[1]);
                    MMA16816(c[mi][2 * pr],     ah[mi], bl4[0], bl4[1]);
                    MMA16816(c[mi][2 * pr],     al[mi], bh4[0], bh4[1]);
                    MMA16816(c[mi][2 * pr + 1], ah[mi], bh4[2], bh4[3]);
                    MMA16816(c[mi][2 * pr + 1], ah[mi], bl4[2], bl4[3]);
                    MMA16816(c[mi][2 * pr + 1], al[mi], bh4[2], bh4[3]);
                }
            }
        }
        __syncthreads();
    }

    const int lr = lane >> 2;
    const int lc = (lane & 3) * 2;
#pragma unroll
    for (int mi = 0; mi < 4; mi++) {
        const int r0 = m0 + wm * 64 + mi * 16 + lr;
#pragma unroll
        for (int ni = 0; ni < 8; ni++) {
            const int col = n0 + wn * 64 + ni * 8 + lc;
            const float b0 = bias[col], b1 = bias[col + 1];
            float2 v0, v1;
            v0.x = c[mi][ni][0] + b0; v0.y = c[mi][ni][1] + b1;
            v1.x = c[mi][ni][2] + b0; v1.y = c[mi][ni][3] + b1;
            *(float2*)&Cm[(size_t)r0 * Ndim + col]       = v0;
            *(float2*)&Cm[(size_t)(r0 + 8) * Ndim + col] = v1;
        }
    }
}

// ---------------------------------------------------------------------------
// Flash attention, register-resident softmax.
// 8 warps x 16 q-rows = 128 rows/CTA; BC=64 kv/tile.
// P repacked from S accumulator frags directly into A-operand frags.
// smem: Qhi 32K | Qlo 32K | Khi 16K | Klo 16K | Vhi 16K | Vlo 16K = 128K.
// ---------------------------------------------------------------------------
#define QHI_O 0u
#define QLO_O 32768u
#define KHI_O 65536u
#define KLO_O 81920u
#define VHI_O 98304u
#define VLO_O 114688u
#define FL_SMEM 131072

__global__ __launch_bounds__(256, 1)
void flash_reg(const float* __restrict__ qkv, float* __restrict__ att)
{
    extern __shared__ __align__(1024) char smf[];
    const uint32_t sb = smem_u32(smf);

    const int tid  = threadIdx.x;
    const int wid  = tid >> 5, lane = tid & 31;
    const int lr   = lane >> 2;            // 0..7
    const int lc   = (lane & 3) << 1;      // 0,2,4,6
    const int b    = blockIdx.x >> 4, h = blockIdx.x & 15;
    const int i0   = ((int)gridDim.y - 1 - (int)blockIdx.y) * 128;
    const size_t RS = (size_t)N1_;
    const float SC = 0.08838834764831844f * 1.44269504088896340736f; // D^-1/2*log2(e)

    const float* qb  = qkv + (size_t)(b * T_ + i0) * RS + h * D_;
    const float* kb0 = qkv + (size_t)b * T_ * RS + C_ + h * D_;
    const float* vb0 = qkv + (size_t)b * T_ * RS + 2 * C_ + h * D_;

    // ---- load Q (scaled, split, swizzled 256B rows) ----
#pragma unroll
    for (int l = 0; l < 16; l++) {
        int idx = tid + l * 256;
        int row = idx >> 5;
        int c   = (idx & 31) << 2;
        float4 v = *(const float4*)(qb + (size_t)row * RS + c);
        v.x *= SC; v.y *= SC; v.z *= SC; v.w *= SC;
        uint32_t h0, h1, l0, l1;
        split4(v, h0, h1, l0, l1);
        uint32_t off = (uint32_t)(row * 256) +
                       (((uint32_t)(c * 2)) ^ ((uint32_t)(row & 7) << 4));
        *(uint2*)(smf + QHI_O + off) = make_uint2(h0, h1);
        *(uint2*)(smf + QLO_O + off) = make_uint2(l0, l1);
    }

    float o[16][4];
#pragma unroll
    for (int ni = 0; ni < 16; ni++)
#pragma unroll
        for (int e = 0; e < 4; e++) o[ni][e] = 0.f;
    float m0r = -1e30f, m1r = -1e30f, L0 = 0.f, L1 = 0.f;

    const uint32_t kxor  = (uint32_t)((lane & 7) << 4);
    const uint32_t aKadd = (uint32_t)((lane >> 4) << 4);
    const uint32_t qRow  = (uint32_t)((wid * 16 + (lane & 15)) * 256);
    // K x4: row = ni2*16 + ((lane>>4)&1)*8 + (lane&7)  (row&7 == lane&7)
    const uint32_t kRowB = (uint32_t)((((lane >> 4) & 1) * 8 + (lane & 7)) * 256);
    const uint32_t bKadd = (uint32_t)(((lane >> 3) & 1) << 4);
    // V x4.trans: row = kb*16 + (lane&15); col pair: +16B for lanes>=16
    const uint32_t vRowB = (uint32_t)((lane & 15) * 256);
    const uint32_t vCadd = (uint32_t)(((lane >> 4) & 1) * 16);

    const int ntiles = i0 / 64 + 2;
    for (int jt = 0; jt < ntiles; jt++) {
        const int j0 = jt * 64;
        __syncthreads();
        // ---- load K/V tile (split, swizzled) ----
#pragma unroll
        for (int l = 0; l < 8; l++) {
            int idx = tid + l * 256;
            int row = idx >> 5;
            int c   = (idx & 31) << 2;
            uint32_t off = (uint32_t)(row * 256) +
                           (((uint32_t)(c * 2)) ^ ((uint32_t)(row & 7) << 4));
            float4 v = *(const float4*)(kb0 + (size_t)(j0 + row) * RS + c);
            uint32_t h0, h1, l0, l1;
            split4(v, h0, h1, l0, l1);
            *(uint2*)(smf + KHI_O + off) = make_uint2(h0, h1);
            *(uint2*)(smf + KLO_O + off) = make_uint2(l0, l1);
            float4 w = *(const float4*)(vb0 + (size_t)(j0 + row) * RS + c);
            split4(w, h0, h1, l0, l1);
            *(uint2*)(smf + VHI_O + off) = make_uint2(h0, h1);
            *(uint2*)(smf + VLO_O + off) = make_uint2(l0, l1);
        }
        __syncthreads();

        // ---- S = Qs @ K^T : 16 x 64 per warp ----
        float s[8][4];
#pragma unroll
        for (int ni = 0; ni < 8; ni++)
#pragma unroll
            for (int e = 0; e < 4; e++) s[ni][e] = 0.f;

#pragma unroll
        for (int ks = 0; ks < 8; ks++) {
            const uint32_t ak = ((uint32_t)(ks * 32) + aKadd) ^ kxor;
            const uint32_t bk = ((uint32_t)(ks * 32) + bKadd) ^ kxor;
            uint32_t qh[4], ql[4];
            LDSM_X4(qh, sb + QHI_O + qRow + ak);
            LDSM_X4(ql, sb + QLO_O + qRow + ak);
#pragma unroll
            for (int n2 = 0; n2 < 4; n2++) {
                uint32_t kh4[4], kl4[4];
                LDSM_X4(kh4, sb + KHI_O + kRowB + (uint32_t)(n2 * 4096) + bk);
                LDSM_X4(kl4, sb + KLO_O + kRowB + (uint32_t)(n2 * 4096) + bk);
                MMA16816(s[2 * n2],     qh, kh4[0], kh4[1]);
                MMA16816(s[2 * n2],     qh, kl4[0], kl4[1]);
                MMA16816(s[2 * n2],     ql, kh4[0], kh4[1]);
                MMA16816(s[2 * n2 + 1], qh, kh4[2], kh4[3]);
                MMA16816(s[2 * n2 + 1], qh, kl4[2], kl4[3]);
                MMA16816(s[2 * n2 + 1], ql, kh4[2], kh4[3]);
            }
        }

        // ---- causal mask near diagonal ----
        if (jt >= ntiles - 2) {
            const int r0 = i0 + wid * 16 + lr;
#pragma unroll
            for (int ni = 0; ni < 8; ni++) {
                int cc = j0 + ni * 8 + lc;
                if (cc     > r0)     s[ni][0] = -1e30f;
                if (cc + 1 > r0)     s[ni][1] = -1e30f;
                if (cc     > r0 + 8) s[ni][2] = -1e30f;
                if (cc + 1 > r0 + 8) s[ni][3] = -1e30f;
            }
        }

        // ---- in-register online softmax (rows lr and lr+8) ----
        float mx0 = -1e30f, mx1 = -1e30f;
#pragma unroll
        for (int ni = 0; ni < 8; ni++) {
            mx0 = fmaxf(mx0, fmaxf(s[ni][0], s[ni][1]));
            mx1 = fmaxf(mx1, fmaxf(s[ni][2], s[ni][3]));
        }
        mx0 = fmaxf(mx0, __shfl_xor_sync(0xffffffffu, mx0, 1));
        mx0 = fmaxf(mx0, __shfl_xor_sync(0xffffffffu, mx0, 2));
        mx1 = fmaxf(mx1, __shfl_xor_sync(0xffffffffu, mx1, 1));
        mx1 = fmaxf(mx1, __shfl_xor_sync(0xffffffffu, mx1, 2));
        const float mn0 = fmaxf(m0r, mx0);
        const float mn1 = fmaxf(m1r, mx1);
        const float co0 = exp2f(m0r - mn0);
        const float co1 = exp2f(m1r - mn1);
        m0r = mn0; m1r = mn1;

        float sum0 = 0.f, sum1 = 0.f;
#pragma unroll
        for (int ni = 0; ni < 8; ni++) {
            float e0 = exp2f(s[ni][0] - mn0);
            float e1 = exp2f(s[ni][1] - mn0);
            float e2 = exp2f(s[ni][2] - mn1);
            float e3 = exp2f(s[ni][3] - mn1);
            sum0 += e0 + e1; sum1 += e2 + e3;
            s[ni][0] = e0; s[ni][1] = e1; s[ni][2] = e2; s[ni][3] = e3;
        }
        sum0 += __shfl_xor_sync(0xffffffffu, sum0, 1);
        sum0 += __shfl_xor_sync(0xffffffffu, sum0, 2);
        sum1 += __shfl_xor_sync(0xffffffffu, sum1, 1);
        sum1 += __shfl_xor_sync(0xffffffffu, sum1, 2);
        L0 = L0 * co0 + sum0;
        L1 = L1 * co1 + sum1;

        // ---- rescale O ----
#pragma unroll
        for (int ni = 0; ni < 16; ni++) {
            o[ni][0] *= co0; o[ni][1] *= co0;
            o[ni][2] *= co1; o[ni][3] *= co1;
        }

        // ---- O += P @ V  (P repacked from S frags; 3-pass) ----
#pragma unroll
        for (int kb = 0; kb < 4; kb++) {
            uint32_t ph[4], pl[4];
            {
                float a0 = s[2 * kb][0],     a1 = s[2 * kb][1];
                float a2 = s[2 * kb][2],     a3 = s[2 * kb][3];
                float b0v = s[2 * kb + 1][0], b1v = s[2 * kb + 1][1];
                float b2v = s[2 * kb + 1][2], b3v = s[2 * kb + 1][3];
                ph[0] = pack_bf2(a0, a1);  ph[1] = pack_bf2(a2, a3);
                ph[2] = pack_bf2(b0v, b1v); ph[3] = pack_bf2(b2v, b3v);
                __nv_bfloat162* t;
                t = (__nv_bfloat162*)&ph[0];
                pl[0] = pack_bf2(a0 - __bfloat162float(t->x), a1 - __bfloat162float(t->y));
                t = (__nv_bfloat162*)&ph[1];
                pl[1] = pack_bf2(a2 - __bfloat162float(t->x), a3 - __bfloat162float(t->y));
                t = (__nv_bfloat162*)&ph[2];
                pl[2] = pack_bf2(b0v - __bfloat162float(t->x), b1v - __bfloat162float(t->y));
                t = (__nv_bfloat162*)&ph[3];
                pl[3] = pack_bf2(b2v - __bfloat162float(t->x), b3v - __bfloat162float(t->y));
            }
            const uint32_t vrb = (uint32_t)(kb * 16 * 256) + vRowB;
#pragma unroll
            for (int n2 = 0; n2 < 8; n2++) {
                uint32_t vh4[4], vl4[4];
                const uint32_t cbo = (((uint32_t)(n2 * 32) + vCadd) ^ kxor);
                LDSM_X4_T(vh4, sb + VHI_O + vrb + cbo);
                LDSM_X4_T(vl4, sb + VLO_O + vrb + cbo);
                MMA16816(o[2 * n2],     ph, vh4[0], vh4[1]);
                MMA16816(o[2 * n2],     ph, vl4[0], vl4[1]);
                MMA16816(o[2 * n2],     pl, vh4[0], vh4[1]);
                MMA16816(o[2 * n2 + 1], ph, vh4[2], vh4[3]);
                MMA16816(o[2 * n2 + 1], ph, vl4[2], vl4[3]);
                MMA16816(o[2 * n2 + 1], pl, vh4[2], vh4[3]);
            }
        }
    }

    // ---- epilogue ----
    {
        const float i0v = 1.f / L0;
        const float i1v = 1.f / L1;
        float* oa = att + (size_t)(b * T_ + i0 + wid * 16 + lr) * C_ + h * D_;
        float* ob = oa + (size_t)8 * C_;
#pragma unroll
        for (int ni = 0; ni < 16; ni++) {
            float2 v0, v1;
            v0.x = o[ni][0] * i0v; v0.y = o[ni][1] * i0v;
            v1.x = o[ni][2] * i1v; v1.y = o[ni][3] * i1v;
            *(float2*)(oa + ni * 8 + lc) = v0;
            *(float2*)(ob + ni * 8 + lc) = v1;
        }
    }
}

// ---------------------------------------------------------------------------
// Launch
// ---------------------------------------------------------------------------
extern "C" void kernel_launch(void* const* d_in, const int* in_sizes, int n_in,
                              void* d_out, int out_size)
{
    const float* x     = (const float*)d_in[0];
    const float* Wqkv  = (const float*)d_in[1];
    const float* bqkv  = (const float*)d_in[2];
    const float* Wproj = (const float*)d_in[3];
    const float* bproj = (const float*)d_in[4];
    float* out = (float*)d_out;

    float *qkv, *att;
    __nv_bfloat16 *xhi, *xlo, *w1hi, *w1lo, *w2hi, *w2lo, *ahi, *alo;
    cudaGetSymbolAddress((void**)&qkv,  g_qkv);
    cudaGetSymbolAddress((void**)&att,  g_att);
    cudaGetSymbolAddress((void**)&xhi,  g_xhi);
    cudaGetSymbolAddress((void**)&xlo,  g_xlo);
    cudaGetSymbolAddress((void**)&w1hi, g_w1hi);
    cudaGetSymbolAddress((void**)&w1lo, g_w1lo);
    cudaGetSymbolAddress((void**)&w2hi, g_w2hi);
    cudaGetSymbolAddress((void**)&w2lo, g_w2lo);
    cudaGetSymbolAddress((void**)&ahi,  g_ahi);
    cudaGetSymbolAddress((void**)&alo,  g_alo);

    cudaFuncSetAttribute(mma_gemm, cudaFuncAttributeMaxDynamicSharedMemorySize,
                         GEMM_SMEM);
    cudaFuncSetAttribute(flash_reg, cudaFuncAttributeMaxDynamicSharedMemorySize,
                         FL_SMEM);

    const int n4x = (M_ * C_) / 4;

    split_kernel<<<n4x / 256, 256>>>(x, xhi, xlo, n4x);
    split_transpose_kernel<<<dim3(N1_ / 32, C_ / 32), dim3(32, 8)>>>(Wqkv, w1hi, w1lo, C_, N1_);
    split_transpose_kernel<<<dim3(C_ / 32, C_ / 32), dim3(32, 8)>>>(Wproj, w2hi, w2lo, C_, C_);

    // 1) qkv = x @ Wqkv + bqkv
    mma_gemm<<<dim3(N1_ / 256, M_ / 128), 256, GEMM_SMEM>>>(
        xhi, xlo, w1hi, w1lo, bqkv, qkv, M_, N1_, C_);

    // 2) causal flash attention (register softmax)
    flash_reg<<<dim3(B_ * H_, T_ / 128), 256, FL_SMEM>>>(qkv, att);

    // 3) split att; out = att @ Wproj + bproj
    split_kernel<<<n4x / 256, 256>>>(att, ahi, alo, n4x);
    mma_gemm<<<dim3(C_ / 256, M_ / 128), 256, GEMM_SMEM>>>(
        ahi, alo, w2hi, w2lo, bproj, out, M_, C_, C_);
}

// round 6
// speedup vs baseline: 3.6737x; 1.0358x over previous
#include <cuda_runtime.h>
#include <cuda_bf16.h>
#include <cstdint>
#include <cstddef>

// Problem constants (B=4, T=2048, C=2048, H=16, D=128)
#define B_  4
#define T_  2048
#define C_  2048
#define H_  16
#define D_  128
#define M_  (B_ * T_)       // 8192
#define N1_ (3 * C_)        // 6144

// softmax scale * log2(e)  (folded into Q at QKV-GEMM epilogue)
#define SC_Q (0.08838834764831844f * 1.44269504088896340736f)

// ---------------------------------------------------------------------------
// Scratch (__device__ globals; no allocs allowed)
// ---------------------------------------------------------------------------
__device__ __nv_bfloat16 g_xhi[(size_t)M_ * C_];
__device__ __nv_bfloat16 g_xlo[(size_t)M_ * C_];
__device__ __nv_bfloat16 g_w1hi[(size_t)N1_ * C_];
__device__ __nv_bfloat16 g_w1lo[(size_t)N1_ * C_];
__device__ __nv_bfloat16 g_w2hi[(size_t)C_ * C_];
__device__ __nv_bfloat16 g_w2lo[(size_t)C_ * C_];
// head-major Q/K/V: [(b*H+h)*T + t]*D + d
__device__ __nv_bfloat16 g_qhi[(size_t)M_ * C_];
__device__ __nv_bfloat16 g_qlo[(size_t)M_ * C_];
__device__ __nv_bfloat16 g_khi[(size_t)M_ * C_];
__device__ __nv_bfloat16 g_klo[(size_t)M_ * C_];
__device__ __nv_bfloat16 g_vhi[(size_t)M_ * C_];
__device__ __nv_bfloat16 g_vlo[(size_t)M_ * C_];
// attention output (token-major [t, C]), feeds proj GEMM
__device__ __nv_bfloat16 g_ahi[(size_t)M_ * C_];
__device__ __nv_bfloat16 g_alo[(size_t)M_ * C_];

// ---------------------------------------------------------------------------
// Helpers
// ---------------------------------------------------------------------------
__device__ __forceinline__ uint32_t smem_u32(const void* p) {
    uint32_t a;
    asm("{ .reg .u64 t; cvta.to.shared.u64 t, %1; cvt.u32.u64 %0, t; }"
        : "=r"(a) : "l"(p));
    return a;
}

#define LDSM_X4(r, a)                                                          \
    asm volatile("ldmatrix.sync.aligned.m8n8.x4.shared.b16 {%0,%1,%2,%3}, [%4];" \
        : "=r"((r)[0]), "=r"((r)[1]), "=r"((r)[2]), "=r"((r)[3]) : "r"(a))

#define LDSM_X4_T(r, a)                                                        \
    asm volatile("ldmatrix.sync.aligned.m8n8.x4.trans.shared.b16 {%0,%1,%2,%3}, [%4];" \
        : "=r"((r)[0]), "=r"((r)[1]), "=r"((r)[2]), "=r"((r)[3]) : "r"(a))

#define MMA16816(c, a, b0v, b1v)                                               \
    asm volatile("mma.sync.aligned.m16n8k16.row.col.f32.bf16.bf16.f32 "        \
        "{%0,%1,%2,%3}, {%4,%5,%6,%7}, {%8,%9}, {%0,%1,%2,%3};"                \
        : "+f"((c)[0]), "+f"((c)[1]), "+f"((c)[2]), "+f"((c)[3])               \
        : "r"((a)[0]), "r"((a)[1]), "r"((a)[2]), "r"((a)[3]),                  \
          "r"(b0v), "r"(b1v))

#define CP_ASYNC16(dst, src)                                                   \
    asm volatile("cp.async.cg.shared.global [%0], [%1], 16;"                   \
        :: "r"(dst), "l"(src))
#define CP_COMMIT()  asm volatile("cp.async.commit_group;" ::: "memory")
#define CP_WAIT1()   asm volatile("cp.async.wait_group 1;" ::: "memory")
#define CP_WAIT0()   asm volatile("cp.async.wait_group 0;" ::: "memory")

__device__ __forceinline__ uint32_t pack_bf2(float a, float b) {
    __nv_bfloat162 t = __halves2bfloat162(__float2bfloat16_rn(a),
                                          __float2bfloat16_rn(b));
    return *(uint32_t*)&t;
}

__device__ __forceinline__ void split4(float4 v, uint32_t& h0, uint32_t& h1,
                                       uint32_t& l0, uint32_t& l1) {
    __nv_bfloat16 ax = __float2bfloat16_rn(v.x);
    __nv_bfloat16 ay = __float2bfloat16_rn(v.y);
    __nv_bfloat16 az = __float2bfloat16_rn(v.z);
    __nv_bfloat16 aw = __float2bfloat16_rn(v.w);
    __nv_bfloat162 th0 = __halves2bfloat162(ax, ay);
    __nv_bfloat162 th1 = __halves2bfloat162(az, aw);
    h0 = *(uint32_t*)&th0;
    h1 = *(uint32_t*)&th1;
    l0 = pack_bf2(v.x - __bfloat162float(ax), v.y - __bfloat162float(ay));
    l1 = pack_bf2(v.z - __bfloat162float(az), v.w - __bfloat162float(aw));
}

// split pair -> hi uint32 + lo uint32
__device__ __forceinline__ void split2(float a, float b, uint32_t& h, uint32_t& l) {
    __nv_bfloat16 ha = __float2bfloat16_rn(a);
    __nv_bfloat16 hb = __float2bfloat16_rn(b);
    __nv_bfloat162 th = __halves2bfloat162(ha, hb);
    h = *(uint32_t*)&th;
    l = pack_bf2(a - __bfloat162float(ha), b - __bfloat162float(hb));
}

// ---------------------------------------------------------------------------
// Split fp32 -> bf16 hi/lo (for x)
// ---------------------------------------------------------------------------
__global__ void split_kernel(const float* __restrict__ in,
                             __nv_bfloat16* __restrict__ hi,
                             __nv_bfloat16* __restrict__ lo, int n4)
{
    int i = blockIdx.x * blockDim.x + threadIdx.x;
    if (i >= n4) return;
    float4 v = ((const float4*)in)[i];
    uint32_t h0, h1, l0, l1;
    split4(v, h0, h1, l0, l1);
    uint32_t* H = (uint32_t*)hi;
    uint32_t* L = (uint32_t*)lo;
    H[2 * i] = h0; H[2 * i + 1] = h1;
    L[2 * i] = l0; L[2 * i + 1] = l1;
}

// ---------------------------------------------------------------------------
// Split + transpose: W[K,N] fp32 -> W^T hi/lo bf16 [N,K]
// ---------------------------------------------------------------------------
__global__ __launch_bounds__(256)
void split_transpose_kernel(const float* __restrict__ W,
                            __nv_bfloat16* __restrict__ hiT,
                            __nv_bfloat16* __restrict__ loT, int K, int N)
{
    __shared__ float t[32][33];
    const int n0 = blockIdx.x * 32, k0 = blockIdx.y * 32;
    const int tx = threadIdx.x, ty = threadIdx.y;
#pragma unroll
    for (int j = 0; j < 4; j++)
        t[ty + j * 8][tx] = W[(size_t)(k0 + ty + j * 8) * N + n0 + tx];
    __syncthreads();
#pragma unroll
    for (int j = 0; j < 4; j++) {
        float v = t[tx][ty + j * 8];
        __nv_bfloat16 h = __float2bfloat16_rn(v);
        __nv_bfloat16 l = __float2bfloat16_rn(v - __bfloat162float(h));
        size_t o = (size_t)(n0 + ty + j * 8) * K + k0 + tx;
        hiT[o] = h;
        loT[o] = l;
    }
}

// ---------------------------------------------------------------------------
// mma.sync split-bf16 GEMM: 128x256 CTA tile, 8 warps of 64x64, K-chunk 64.
// MODE 0: fp32 out + bias (proj).
// MODE 1: QKV epilogue — write bf16 hi/lo Q(scaled)/K/V head-major.
// ---------------------------------------------------------------------------
#define G_STAGE 98304u
#define GEMM_SMEM (2 * 98304)

__device__ __forceinline__ void load_chunk2(uint32_t sb, int buf,
                                            const __nv_bfloat16* aHi,
                                            const __nv_bfloat16* aLo,
                                            const __nv_bfloat16* bHi,
                                            const __nv_bfloat16* bLo,
                                            int k0, int Kdim, int tid)
{
    const uint32_t st = sb + (uint32_t)buf * G_STAGE;
    {
        const __nv_bfloat16* srcs[2] = { aHi, aLo };
#pragma unroll
        for (int tl = 0; tl < 2; tl++) {
            const __nv_bfloat16* s = srcs[tl] + k0;
            const uint32_t tb = st + (uint32_t)tl * 16384u;
#pragma unroll
            for (int l = 0; l < 4; l++) {
                int idx = tid + l * 256;
                int row = idx >> 3, seg = idx & 7;
                CP_ASYNC16(tb + (uint32_t)(row * 128 + ((seg * 16) ^ ((row & 7) << 4))),
                           s + (size_t)row * Kdim + seg * 8);
            }
        }
    }
    {
        const __nv_bfloat16* srcs[2] = { bHi, bLo };
#pragma unroll
        for (int tl = 0; tl < 2; tl++) {
            const __nv_bfloat16* s = srcs[tl] + k0;
            const uint32_t tb = st + 32768u + (uint32_t)tl * 32768u;
#pragma unroll
            for (int l = 0; l < 8; l++) {
                int idx = tid + l * 256;
                int row = idx >> 3, seg = idx & 7;
                CP_ASYNC16(tb + (uint32_t)(row * 128 + ((seg * 16) ^ ((row & 7) << 4))),
                           s + (size_t)row * Kdim + seg * 8);
            }
        }
    }
    CP_COMMIT();
}

template <int MODE>
__global__ __launch_bounds__(256, 1)
void mma_gemm(const __nv_bfloat16* __restrict__ Ahi, const __nv_bfloat16* __restrict__ Alo,
              const __nv_bfloat16* __restrict__ Bhi, const __nv_bfloat16* __restrict__ Blo,
              const float* __restrict__ bias, float* __restrict__ Cm,
              __nv_bfloat16* __restrict__ qhi, __nv_bfloat16* __restrict__ qlo,
              __nv_bfloat16* __restrict__ khi, __nv_bfloat16* __restrict__ klo,
              __nv_bfloat16* __restrict__ vhi, __nv_bfloat16* __restrict__ vlo,
              int Ndim, int Kdim)
{
    extern __shared__ __align__(128) char smem[];
    const uint32_t sb = smem_u32(smem);
    const int tid  = threadIdx.x;
    const int wid  = tid >> 5;
    const int lane = tid & 31;
    const int wm   = wid & 1;
    const int wn   = wid >> 1;
    const int m0   = blockIdx.y * 128;
    const int n0   = blockIdx.x * 256;

    const __nv_bfloat16* aHi = Ahi + (size_t)m0 * Kdim;
    const __nv_bfloat16* aLo = Alo + (size_t)m0 * Kdim;
    const __nv_bfloat16* bHi = Bhi + (size_t)n0 * Kdim;
    const __nv_bfloat16* bLo = Blo + (size_t)n0 * Kdim;

    const uint32_t kxor    = (uint32_t)((lane & 7) << 4);
    const uint32_t aRowOff = (uint32_t)((wm * 64 + (lane & 15)) * 128);
    const uint32_t aKadd   = (uint32_t)((lane >> 4) * 16);
    const uint32_t bRowOff = (uint32_t)((wn * 64 + ((lane >> 4) & 1) * 8 + (lane & 7)) * 128);
    const uint32_t bKadd   = (uint32_t)(((lane >> 3) & 1) * 16);

    float c[4][8][4];
#pragma unroll
    for (int mi = 0; mi < 4; mi++)
#pragma unroll
        for (int ni = 0; ni < 8; ni++)
#pragma unroll
            for (int e = 0; e < 4; e++) c[mi][ni][e] = 0.f;

    const int nch = Kdim >> 6;
    load_chunk2(sb, 0, aHi, aLo, bHi, bLo, 0, Kdim, tid);

    for (int t = 0; t < nch; t++) {
        if (t + 1 < nch) {
            load_chunk2(sb, (t + 1) & 1, aHi, aLo, bHi, bLo, (t + 1) << 6, Kdim, tid);
            CP_WAIT1();
        } else {
            CP_WAIT0();
        }
        __syncthreads();

        const uint32_t st  = sb + (uint32_t)(t & 1) * G_STAGE;
        const uint32_t tAh = st;
        const uint32_t tAl = st + 16384u;
        const uint32_t tBh = st + 32768u;
        const uint32_t tBl = st + 65536u;

#pragma unroll
        for (int ks = 0; ks < 4; ks++) {
            const uint32_t aK = ((uint32_t)(ks * 32) + aKadd) ^ kxor;
            const uint32_t bK = ((uint32_t)(ks * 32) + bKadd) ^ kxor;
            uint32_t ah[4][4], al[4][4];
#pragma unroll
            for (int mi = 0; mi < 4; mi++) {
                LDSM_X4(ah[mi], tAh + aRowOff + (uint32_t)(mi * 2048) + aK);
                LDSM_X4(al[mi], tAl + aRowOff + (uint32_t)(mi * 2048) + aK);
            }
#pragma unroll
            for (int pr = 0; pr < 4; pr++) {
                uint32_t bh4[4], bl4[4];
                LDSM_X4(bh4, tBh + bRowOff + (uint32_t)(pr * 2048) + bK);
                LDSM_X4(bl4, tBl + bRowOff + (uint32_t)(pr * 2048) + bK);
                // pass 1: ah * bh  (reuse distance 8)
#pragma unroll
                for (int mi = 0; mi < 4; mi++) {
                    MMA16816(c[mi][2 * pr],     ah[mi], bh4[0], bh4[1]);
                    MMA16816(c[mi][2 * pr + 1], ah[mi], bh4[2], bh4[3]);
                }
                // pass 2: ah * bl
#pragma unroll
                for (int mi = 0; mi < 4; mi++) {
                    MMA16816(c[mi][2 * pr],     ah[mi], bl4[0], bl4[1]);
                    MMA16816(c[mi][2 * pr + 1], ah[mi], bl4[2], bl4[3]);
                }
                // pass 3: al * bh
#pragma unroll
                for (int mi = 0; mi < 4; mi++) {
                    MMA16816(c[mi][2 * pr],     al[mi], bh4[0], bh4[1]);
                    MMA16816(c[mi][2 * pr + 1], al[mi], bh4[2], bh4[3]);
                }
            }
        }
        __syncthreads();
    }

    const int lr = lane >> 2;
    const int lc = (lane & 3) * 2;

    if (MODE == 0) {
#pragma unroll
        for (int mi = 0; mi < 4; mi++) {
            const int r0 = m0 + wm * 64 + mi * 16 + lr;
#pragma unroll
            for (int ni = 0; ni < 8; ni++) {
                const int col = n0 + wn * 64 + ni * 8 + lc;
                const float b0 = bias[col], b1 = bias[col + 1];
                float2 v0, v1;
                v0.x = c[mi][ni][0] + b0; v0.y = c[mi][ni][1] + b1;
                v1.x = c[mi][ni][2] + b0; v1.y = c[mi][ni][3] + b1;
                *(float2*)&Cm[(size_t)r0 * Ndim + col]       = v0;
                *(float2*)&Cm[(size_t)(r0 + 8) * Ndim + col] = v1;
            }
        }
    } else {
        // QKV epilogue: write hi/lo bf16 head-major [(b*H+h)*T + t]*D + d
        const int colbase = n0 + wn * 64;
        const int region  = colbase >> 11;          // 0=Q,1=K,2=V
        const int cr      = colbase & 2047;
        const int hh      = cr >> 7;
        const int dbase   = cr & 127;               // 0 or 64
        const float scale = (region == 0) ? SC_Q : 1.f;
        __nv_bfloat16 *dh, *dl;
        if (region == 0)      { dh = qhi; dl = qlo; }
        else if (region == 1) { dh = khi; dl = klo; }
        else                  { dh = vhi; dl = vlo; }
#pragma unroll
        for (int mi = 0; mi < 4; mi++) {
            const int r0 = m0 + wm * 64 + mi * 16 + lr;   // token index b*T + t
#pragma unroll
            for (int half = 0; half < 2; half++) {
                const int row = r0 + half * 8;
                const int bb  = row >> 11;
                const int tt  = row & 2047;
                const size_t base = (((size_t)(bb * H_ + hh)) * T_ + tt) * D_ + dbase;
#pragma unroll
                for (int ni = 0; ni < 8; ni++) {
                    const int col = colbase + ni * 8 + lc;
                    float v0 = (c[mi][ni][2 * half]     + bias[col])     * scale;
                    float v1 = (c[mi][ni][2 * half + 1] + bias[col + 1]) * scale;
                    uint32_t hv, lv;
                    split2(v0, v1, hv, lv);
                    *(uint32_t*)&dh[base + ni * 8 + lc] = hv;
                    *(uint32_t*)&dl[base + ni * 8 + lc] = lv;
                }
            }
        }
    }
}

// ---------------------------------------------------------------------------
// Flash attention: register softmax, bf16 hi/lo operands straight from gmem,
// double-buffered cp.async K/V pipeline. 8 warps x 16 q-rows; BC=64.
// smem: Qhi 32K | Qlo 32K | 2 KV stages of (Khi|Klo|Vhi|Vlo = 64K) = 192K.
// ---------------------------------------------------------------------------
#define FQ_HI 0u
#define FQ_LO 32768u
#define FKV0  65536u
#define FKV_STAGE 65536u
#define FL_SMEM 196608

__device__ __forceinline__ void flash_load_kv(uint32_t sb, uint32_t stage,
                                              const __nv_bfloat16* kh_g,
                                              const __nv_bfloat16* kl_g,
                                              const __nv_bfloat16* vh_g,
                                              const __nv_bfloat16* vl_g,
                                              int j0, int tid)
{
    const __nv_bfloat16* srcs[4] = {
        kh_g + (size_t)j0 * D_, kl_g + (size_t)j0 * D_,
        vh_g + (size_t)j0 * D_, vl_g + (size_t)j0 * D_
    };
#pragma unroll
    for (int l = 0; l < 16; l++) {
        int idx  = tid + l * 256;
        int tile = idx >> 10;           // constant per unrolled l
        int rem  = idx & 1023;
        int row  = rem >> 4;
        int seg  = rem & 15;
        CP_ASYNC16(sb + stage + (uint32_t)(tile * 16384) +
                       (uint32_t)(row * 256 + ((seg * 16) ^ ((row & 7) << 4))),
                   srcs[tile] + (size_t)row * D_ + seg * 8);
    }
    CP_COMMIT();
}

__global__ __launch_bounds__(256, 1)
void flash_reg(const __nv_bfloat16* __restrict__ qhi, const __nv_bfloat16* __restrict__ qlo,
               const __nv_bfloat16* __restrict__ khi, const __nv_bfloat16* __restrict__ klo,
               const __nv_bfloat16* __restrict__ vhi, const __nv_bfloat16* __restrict__ vlo,
               __nv_bfloat16* __restrict__ ahi, __nv_bfloat16* __restrict__ alo)
{
    extern __shared__ __align__(1024) char smf[];
    const uint32_t sb = smem_u32(smf);

    const int tid  = threadIdx.x;
    const int wid  = tid >> 5, lane = tid & 31;
    const int lr   = lane >> 2;
    const int lc   = (lane & 3) << 1;
    const int b    = blockIdx.x >> 4, h = blockIdx.x & 15;
    const int i0   = ((int)gridDim.y - 1 - (int)blockIdx.y) * 128;

    const size_t headoff = ((size_t)(b * H_ + h)) * T_ * D_;
    const __nv_bfloat16* qh_g = qhi + headoff + (size_t)i0 * D_;
    const __nv_bfloat16* ql_g = qlo + headoff + (size_t)i0 * D_;
    const __nv_bfloat16* kh_g = khi + headoff;
    const __nv_bfloat16* kl_g = klo + headoff;
    const __nv_bfloat16* vh_g = vhi + headoff;
    const __nv_bfloat16* vl_g = vlo + headoff;

    // ---- Q tiles via cp.async (group together with kv tile 0) ----
    {
        const __nv_bfloat16* srcs[2] = { qh_g, ql_g };
#pragma unroll
        for (int l = 0; l < 16; l++) {
            int idx  = tid + l * 256;
            int tile = idx >> 11;       // constant per unrolled l
            int rem  = idx & 2047;
            int row  = rem >> 4;
            int seg  = rem & 15;
            CP_ASYNC16(sb + (uint32_t)(tile * 32768) +
                           (uint32_t)(row * 256 + ((seg * 16) ^ ((row & 7) << 4))),
                       srcs[tile] + (size_t)row * D_ + seg * 8);
        }
    }
    flash_load_kv(sb, FKV0, kh_g, kl_g, vh_g, vl_g, 0, tid);  // commits Q+kv0

    float o[16][4];
#pragma unroll
    for (int ni = 0; ni < 16; ni++)
#pragma unroll
        for (int e = 0; e < 4; e++) o[ni][e] = 0.f;
    float m0r = -1e30f, m1r = -1e30f, L0 = 0.f, L1 = 0.f;

    const uint32_t kxor  = (uint32_t)((lane & 7) << 4);
    const uint32_t aKadd = (uint32_t)((lane >> 4) << 4);
    const uint32_t qRow  = (uint32_t)((wid * 16 + (lane & 15)) * 256);
    const uint32_t kRowB = (uint32_t)((((lane >> 4) & 1) * 8 + (lane & 7)) * 256);
    const uint32_t bKadd = (uint32_t)(((lane >> 3) & 1) << 4);
    const uint32_t vRowB = (uint32_t)((lane & 15) * 256);
    const uint32_t vCadd = (uint32_t)(((lane >> 4) & 1) * 16);

    const int ntiles = i0 / 64 + 2;
    for (int jt = 0; jt < ntiles; jt++) {
        const int j0 = jt * 64;
        if (jt + 1 < ntiles) {
            flash_load_kv(sb, FKV0 + (uint32_t)((jt + 1) & 1) * FKV_STAGE,
                          kh_g, kl_g, vh_g, vl_g, (jt + 1) * 64, tid);
            CP_WAIT1();
        } else {
            CP_WAIT0();
        }
        __syncthreads();

        const uint32_t stg   = FKV0 + (uint32_t)(jt & 1) * FKV_STAGE;
        const uint32_t sKhi  = stg;
        const uint32_t sKlo  = stg + 16384u;
        const uint32_t sVhi  = stg + 32768u;
        const uint32_t sVlo  = stg + 49152u;

        // ---- S = Qs @ K^T : 16 x 64 per warp ----
        float s[8][4];
#pragma unroll
        for (int ni = 0; ni < 8; ni++)
#pragma unroll
            for (int e = 0; e < 4; e++) s[ni][e] = 0.f;

#pragma unroll
        for (int ks = 0; ks < 8; ks++) {
            const uint32_t ak = ((uint32_t)(ks * 32) + aKadd) ^ kxor;
            const uint32_t bk = ((uint32_t)(ks * 32) + bKadd) ^ kxor;
            uint32_t qh[4], ql[4];
            LDSM_X4(qh, sb + FQ_HI + qRow + ak);
            LDSM_X4(ql, sb + FQ_LO + qRow + ak);
#pragma unroll
            for (int n2 = 0; n2 < 4; n2++) {
                uint32_t kh4[4], kl4[4];
                LDSM_X4(kh4, sb + sKhi + kRowB + (uint32_t)(n2 * 4096) + bk);
                LDSM_X4(kl4, sb + sKlo + kRowB + (uint32_t)(n2 * 4096) + bk);
                MMA16816(s[2 * n2],     qh, kh4[0], kh4[1]);
                MMA16816(s[2 * n2 + 1], qh, kh4[2], kh4[3]);
                MMA16816(s[2 * n2],     qh, kl4[0], kl4[1]);
                MMA16816(s[2 * n2 + 1], qh, kl4[2], kl4[3]);
                MMA16816(s[2 * n2],     ql, kh4[0], kh4[1]);
                MMA16816(s[2 * n2 + 1], ql, kh4[2], kh4[3]);
            }
        }

        // ---- causal mask near diagonal ----
        if (jt >= ntiles - 2) {
            const int r0 = i0 + wid * 16 + lr;
#pragma unroll
            for (int ni = 0; ni < 8; ni++) {
                int cc = j0 + ni * 8 + lc;
                if (cc     > r0)     s[ni][0] = -1e30f;
                if (cc + 1 > r0)     s[ni][1] = -1e30f;
                if (cc     > r0 + 8) s[ni][2] = -1e30f;
                if (cc + 1 > r0 + 8) s[ni][3] = -1e30f;
            }
        }

        // ---- in-register online softmax ----
        float mx0 = -1e30f, mx1 = -1e30f;
#pragma unroll
        for (int ni = 0; ni < 8; ni++) {
            mx0 = fmaxf(mx0, fmaxf(s[ni][0], s[ni][1]));
            mx1 = fmaxf(mx1, fmaxf(s[ni][2], s[ni][3]));
        }
        mx0 = fmaxf(mx0, __shfl_xor_sync(0xffffffffu, mx0, 1));
        mx0 = fmaxf(mx0, __shfl_xor_sync(0xffffffffu, mx0, 2));
        mx1 = fmaxf(mx1, __shfl_xor_sync(0xffffffffu, mx1, 1));
        mx1 = fmaxf(mx1, __shfl_xor_sync(0xffffffffu, mx1, 2));
        const float mn0 = fmaxf(m0r, mx0);
        const float mn1 = fmaxf(m1r, mx1);
        const float co0 = exp2f(m0r - mn0);
        const float co1 = exp2f(m1r - mn1);
        m0r = mn0; m1r = mn1;

        float sum0 = 0.f, sum1 = 0.f;
#pragma unroll
        for (int ni = 0; ni < 8; ni++) {
            float e0 = exp2f(s[ni][0] - mn0);
            float e1 = exp2f(s[ni][1] - mn0);
            float e2 = exp2f(s[ni][2] - mn1);
            float e3 = exp2f(s[ni][3] - mn1);
            sum0 += e0 + e1; sum1 += e2 + e3;
            s[ni][0] = e0; s[ni][1] = e1; s[ni][2] = e2; s[ni][3] = e3;
        }
        sum0 += __shfl_xor_sync(0xffffffffu, sum0, 1);
        sum0 += __shfl_xor_sync(0xffffffffu, sum0, 2);
        sum1 += __shfl_xor_sync(0xffffffffu, sum1, 1);
        sum1 += __shfl_xor_sync(0xffffffffu, sum1, 2);
        L0 = L0 * co0 + sum0;
        L1 = L1 * co1 + sum1;

        // ---- rescale O ----
#pragma unroll
        for (int ni = 0; ni < 16; ni++) {
            o[ni][0] *= co0; o[ni][1] *= co0;
            o[ni][2] *= co1; o[ni][3] *= co1;
        }

        // ---- O += P @ V  (P repacked from S frags; 3-pass) ----
#pragma unroll
        for (int kb = 0; kb < 4; kb++) {
            uint32_t ph[4], pl[4];
            split2(s[2 * kb][0],     s[2 * kb][1],     ph[0], pl[0]);
            split2(s[2 * kb][2],     s[2 * kb][3],     ph[1], pl[1]);
            split2(s[2 * kb + 1][0], s[2 * kb + 1][1], ph[2], pl[2]);
            split2(s[2 * kb + 1][2], s[2 * kb + 1][3], ph[3], pl[3]);
            const uint32_t vrb = (uint32_t)(kb * 16 * 256) + vRowB;
#pragma unroll
            for (int n2 = 0; n2 < 8; n2++) {
                uint32_t vh4[4], vl4[4];
                const uint32_t cbo = (((uint32_t)(n2 * 32) + vCadd) ^ kxor);
                LDSM_X4_T(vh4, sb + sVhi + vrb + cbo);
                LDSM_X4_T(vl4, sb + sVlo + vrb + cbo);
                MMA16816(o[2 * n2],     ph, vh4[0], vh4[1]);
                MMA16816(o[2 * n2 + 1], ph, vh4[2], vh4[3]);
                MMA16816(o[2 * n2],     ph, vl4[0], vl4[1]);
                MMA16816(o[2 * n2 + 1], ph, vl4[2], vl4[3]);
                MMA16816(o[2 * n2],     pl, vh4[0], vh4[1]);
                MMA16816(o[2 * n2 + 1], pl, vh4[2], vh4[3]);
            }
        }
        __syncthreads();
    }

    // ---- epilogue: normalize, split to bf16 hi/lo, token-major [t, C] ----
    {
        const float i0v = 1.f / L0;
        const float i1v = 1.f / L1;
        const size_t ra = (size_t)(b * T_ + i0 + wid * 16 + lr) * C_ + h * D_;
        const size_t rb = ra + (size_t)8 * C_;
#pragma unroll
        for (int ni = 0; ni < 16; ni++) {
            uint32_t hv, lv;
            split2(o[ni][0] * i0v, o[ni][1] * i0v, hv, lv);
            *(uint32_t*)&ahi[ra + ni * 8 + lc] = hv;
            *(uint32_t*)&alo[ra + ni * 8 + lc] = lv;
            split2(o[ni][2] * i1v, o[ni][3] * i1v, hv, lv);
            *(uint32_t*)&ahi[rb + ni * 8 + lc] = hv;
            *(uint32_t*)&alo[rb + ni * 8 + lc] = lv;
        }
    }
}

// ---------------------------------------------------------------------------
// Launch
// ---------------------------------------------------------------------------
extern "C" void kernel_launch(void* const* d_in, const int* in_sizes, int n_in,
                              void* d_out, int out_size)
{
    const float* x     = (const float*)d_in[0];
    const float* Wqkv  = (const float*)d_in[1];
    const float* bqkv  = (const float*)d_in[2];
    const float* Wproj = (const float*)d_in[3];
    const float* bproj = (const float*)d_in[4];
    float* out = (float*)d_out;

    __nv_bfloat16 *xhi, *xlo, *w1hi, *w1lo, *w2hi, *w2lo;
    __nv_bfloat16 *qhi, *qlo, *khi, *klo, *vhi, *vlo, *ahi, *alo;
    cudaGetSymbolAddress((void**)&xhi,  g_xhi);
    cudaGetSymbolAddress((void**)&xlo,  g_xlo);
    cudaGetSymbolAddress((void**)&w1hi, g_w1hi);
    cudaGetSymbolAddress((void**)&w1lo, g_w1lo);
    cudaGetSymbolAddress((void**)&w2hi, g_w2hi);
    cudaGetSymbolAddress((void**)&w2lo, g_w2lo);
    cudaGetSymbolAddress((void**)&qhi,  g_qhi);
    cudaGetSymbolAddress((void**)&qlo,  g_qlo);
    cudaGetSymbolAddress((void**)&khi,  g_khi);
    cudaGetSymbolAddress((void**)&klo,  g_klo);
    cudaGetSymbolAddress((void**)&vhi,  g_vhi);
    cudaGetSymbolAddress((void**)&vlo,  g_vlo);
    cudaGetSymbolAddress((void**)&ahi,  g_ahi);
    cudaGetSymbolAddress((void**)&alo,  g_alo);

    cudaFuncSetAttribute(mma_gemm<0>, cudaFuncAttributeMaxDynamicSharedMemorySize,
                         GEMM_SMEM);
    cudaFuncSetAttribute(mma_gemm<1>, cudaFuncAttributeMaxDynamicSharedMemorySize,
                         GEMM_SMEM);
    cudaFuncSetAttribute(flash_reg, cudaFuncAttributeMaxDynamicSharedMemorySize,
                         FL_SMEM);

    const int n4x = (M_ * C_) / 4;

    split_kernel<<<n4x / 256, 256>>>(x, xhi, xlo, n4x);
    split_transpose_kernel<<<dim3(N1_ / 32, C_ / 32), dim3(32, 8)>>>(Wqkv, w1hi, w1lo, C_, N1_);
    split_transpose_kernel<<<dim3(C_ / 32, C_ / 32), dim3(32, 8)>>>(Wproj, w2hi, w2lo, C_, C_);

    // 1) QKV GEMM -> split bf16 Q(scaled)/K/V head-major
    mma_gemm<1><<<dim3(N1_ / 256, M_ / 128), 256, GEMM_SMEM>>>(
        xhi, xlo, w1hi, w1lo, bqkv, nullptr,
        qhi, qlo, khi, klo, vhi, vlo, N1_, C_);

    // 2) causal flash attention -> split bf16 att
    flash_reg<<<dim3(B_ * H_, T_ / 128), 256, FL_SMEM>>>(
        qhi, qlo, khi, klo, vhi, vlo, ahi, alo);

    // 3) proj GEMM -> fp32 out
    mma_gemm<0><<<dim3(C_ / 256, M_ / 128), 256, GEMM_SMEM>>>(
        ahi, alo, w2hi, w2lo, bproj, out,
        nullptr, nullptr, nullptr, nullptr, nullptr, nullptr, C_, C_);
}

// round 7
// speedup vs baseline: 3.9544x; 1.0764x over previous
#include <cuda_runtime.h>
#include <cuda_bf16.h>
#include <cstdint>
#include <cstddef>

// Problem constants (B=4, T=2048, C=2048, H=16, D=128)
#define B_  4
#define T_  2048
#define C_  2048
#define H_  16
#define D_  128
#define M_  (B_ * T_)       // 8192
#define N1_ (3 * C_)        // 6144

// softmax scale * log2(e)  (folded into Q at QKV-GEMM epilogue)
#define SC_Q (0.08838834764831844f * 1.44269504088896340736f)

// ---------------------------------------------------------------------------
// Scratch (__device__ globals; no allocs allowed)
// ---------------------------------------------------------------------------
__device__ __nv_bfloat16 g_xhi[(size_t)M_ * C_];
__device__ __nv_bfloat16 g_xlo[(size_t)M_ * C_];
__device__ __nv_bfloat16 g_w1hi[(size_t)N1_ * C_];
__device__ __nv_bfloat16 g_w1lo[(size_t)N1_ * C_];
__device__ __nv_bfloat16 g_w2hi[(size_t)C_ * C_];
__device__ __nv_bfloat16 g_w2lo[(size_t)C_ * C_];
// head-major Q/K/V: [(b*H+h)*T + t]*D + d
__device__ __nv_bfloat16 g_qhi[(size_t)M_ * C_];
__device__ __nv_bfloat16 g_qlo[(size_t)M_ * C_];
__device__ __nv_bfloat16 g_khi[(size_t)M_ * C_];
__device__ __nv_bfloat16 g_klo[(size_t)M_ * C_];
__device__ __nv_bfloat16 g_vhi[(size_t)M_ * C_];
__device__ __nv_bfloat16 g_vlo[(size_t)M_ * C_];
// attention output (token-major [t, C]), feeds proj GEMM
__device__ __nv_bfloat16 g_ahi[(size_t)M_ * C_];
__device__ __nv_bfloat16 g_alo[(size_t)M_ * C_];

// ---------------------------------------------------------------------------
// Helpers
// ---------------------------------------------------------------------------
__device__ __forceinline__ uint32_t smem_u32(const void* p) {
    uint32_t a;
    asm("{ .reg .u64 t; cvta.to.shared.u64 t, %1; cvt.u32.u64 %0, t; }"
        : "=r"(a) : "l"(p));
    return a;
}

#define LDSM_X4(r, a)                                                          \
    asm volatile("ldmatrix.sync.aligned.m8n8.x4.shared.b16 {%0,%1,%2,%3}, [%4];" \
        : "=r"((r)[0]), "=r"((r)[1]), "=r"((r)[2]), "=r"((r)[3]) : "r"(a))

#define LDSM_X4_T(r, a)                                                        \
    asm volatile("ldmatrix.sync.aligned.m8n8.x4.trans.shared.b16 {%0,%1,%2,%3}, [%4];" \
        : "=r"((r)[0]), "=r"((r)[1]), "=r"((r)[2]), "=r"((r)[3]) : "r"(a))

#define MMA16816(c, a, b0v, b1v)                                               \
    asm volatile("mma.sync.aligned.m16n8k16.row.col.f32.bf16.bf16.f32 "        \
        "{%0,%1,%2,%3}, {%4,%5,%6,%7}, {%8,%9}, {%0,%1,%2,%3};"                \
        : "+f"((c)[0]), "+f"((c)[1]), "+f"((c)[2]), "+f"((c)[3])               \
        : "r"((a)[0]), "r"((a)[1]), "r"((a)[2]), "r"((a)[3]),                  \
          "r"(b0v), "r"(b1v))

#define CP_ASYNC16(dst, src)                                                   \
    asm volatile("cp.async.cg.shared.global [%0], [%1], 16;"                   \
        :: "r"(dst), "l"(src))
#define CP_COMMIT()  asm volatile("cp.async.commit_group;" ::: "memory")
#define CP_WAIT1()   asm volatile("cp.async.wait_group 1;" ::: "memory")
#define CP_WAIT0()   asm volatile("cp.async.wait_group 0;" ::: "memory")

__device__ __forceinline__ uint32_t pack_bf2(float a, float b) {
    __nv_bfloat162 t = __halves2bfloat162(__float2bfloat16_rn(a),
                                          __float2bfloat16_rn(b));
    return *(uint32_t*)&t;
}

__device__ __forceinline__ void split4(float4 v, uint32_t& h0, uint32_t& h1,
                                       uint32_t& l0, uint32_t& l1) {
    __nv_bfloat16 ax = __float2bfloat16_rn(v.x);
    __nv_bfloat16 ay = __float2bfloat16_rn(v.y);
    __nv_bfloat16 az = __float2bfloat16_rn(v.z);
    __nv_bfloat16 aw = __float2bfloat16_rn(v.w);
    __nv_bfloat162 th0 = __halves2bfloat162(ax, ay);
    __nv_bfloat162 th1 = __halves2bfloat162(az, aw);
    h0 = *(uint32_t*)&th0;
    h1 = *(uint32_t*)&th1;
    l0 = pack_bf2(v.x - __bfloat162float(ax), v.y - __bfloat162float(ay));
    l1 = pack_bf2(v.z - __bfloat162float(az), v.w - __bfloat162float(aw));
}

__device__ __forceinline__ void split2(float a, float b, uint32_t& h, uint32_t& l) {
    __nv_bfloat16 ha = __float2bfloat16_rn(a);
    __nv_bfloat16 hb = __float2bfloat16_rn(b);
    __nv_bfloat162 th = __halves2bfloat162(ha, hb);
    h = *(uint32_t*)&th;
    l = pack_bf2(a - __bfloat162float(ha), b - __bfloat162float(hb));
}

// ---------------------------------------------------------------------------
// Split fp32 -> bf16 hi/lo (for x)
// ---------------------------------------------------------------------------
__global__ void split_kernel(const float* __restrict__ in,
                             __nv_bfloat16* __restrict__ hi,
                             __nv_bfloat16* __restrict__ lo, int n4)
{
    int i = blockIdx.x * blockDim.x + threadIdx.x;
    if (i >= n4) return;
    float4 v = ((const float4*)in)[i];
    uint32_t h0, h1, l0, l1;
    split4(v, h0, h1, l0, l1);
    uint32_t* H = (uint32_t*)hi;
    uint32_t* L = (uint32_t*)lo;
    H[2 * i] = h0; H[2 * i + 1] = h1;
    L[2 * i] = l0; L[2 * i + 1] = l1;
}

// ---------------------------------------------------------------------------
// Split + transpose: W[K,N] fp32 -> W^T hi/lo bf16 [N,K]
// ---------------------------------------------------------------------------
__global__ __launch_bounds__(256)
void split_transpose_kernel(const float* __restrict__ W,
                            __nv_bfloat16* __restrict__ hiT,
                            __nv_bfloat16* __restrict__ loT, int K, int N)
{
    __shared__ float t[32][33];
    const int n0 = blockIdx.x * 32, k0 = blockIdx.y * 32;
    const int tx = threadIdx.x, ty = threadIdx.y;
#pragma unroll
    for (int j = 0; j < 4; j++)
        t[ty + j * 8][tx] = W[(size_t)(k0 + ty + j * 8) * N + n0 + tx];
    __syncthreads();
#pragma unroll
    for (int j = 0; j < 4; j++) {
        float v = t[tx][ty + j * 8];
        __nv_bfloat16 h = __float2bfloat16_rn(v);
        __nv_bfloat16 l = __float2bfloat16_rn(v - __bfloat162float(h));
        size_t o = (size_t)(n0 + ty + j * 8) * K + k0 + tx;
        hiT[o] = h;
        loT[o] = l;
    }
}

// ---------------------------------------------------------------------------
// mma.sync split-bf16 GEMM, 2 CTAs/SM version:
// CTA tile 128x128, 8 warps of 64x32, K-chunk 32, double-buffered.
// SMEM/stage: Ahi 8K | Alo 8K | Bhi 8K | Blo 8K = 32K; 2 stages = 64K/CTA.
// 64B rows, swizzle: (seg*16) ^ (((row>>1)&3)<<4)  -> conflict-free ldsm.
// MODE 0: fp32 out + bias (proj). MODE 1: QKV split-bf16 head-major epilogue.
// ---------------------------------------------------------------------------
#define GK_STAGE 32768u
#define GEMM_SMEM (2 * 32768)

#define SW64(row, segb) ((uint32_t)((row) * 64) + (((uint32_t)(segb)) ^ ((((uint32_t)(row) >> 1) & 3u) << 4)))

__device__ __forceinline__ void load_chunk32(uint32_t sb, int buf,
                                             const __nv_bfloat16* aHi,
                                             const __nv_bfloat16* aLo,
                                             const __nv_bfloat16* bHi,
                                             const __nv_bfloat16* bLo,
                                             int k0, int Kdim, int tid)
{
    const uint32_t st = sb + (uint32_t)buf * GK_STAGE;
    const __nv_bfloat16* srcs[4] = { aHi, aLo, bHi, bLo };
#pragma unroll
    for (int tl = 0; tl < 4; tl++) {
        const __nv_bfloat16* s = srcs[tl] + k0;
        const uint32_t tb = st + (uint32_t)tl * 8192u;
#pragma unroll
        for (int l = 0; l < 2; l++) {
            int idx = tid + l * 256;          // 512 slots: 128 rows x 4 segs
            int row = idx >> 2, seg = idx & 3;
            CP_ASYNC16(tb + SW64(row, seg * 16),
                       s + (size_t)row * Kdim + seg * 8);
        }
    }
    CP_COMMIT();
}

template <int MODE>
__global__ __launch_bounds__(256, 2)
void mma_gemm(const __nv_bfloat16* __restrict__ Ahi, const __nv_bfloat16* __restrict__ Alo,
              const __nv_bfloat16* __restrict__ Bhi, const __nv_bfloat16* __restrict__ Blo,
              const float* __restrict__ bias, float* __restrict__ Cm,
              __nv_bfloat16* __restrict__ qhi, __nv_bfloat16* __restrict__ qlo,
              __nv_bfloat16* __restrict__ khi, __nv_bfloat16* __restrict__ klo,
              __nv_bfloat16* __restrict__ vhi, __nv_bfloat16* __restrict__ vlo,
              int Ndim, int Kdim)
{
    extern __shared__ __align__(128) char smem[];
    const uint32_t sb = smem_u32(smem);
    const int tid  = threadIdx.x;
    const int wid  = tid >> 5;
    const int lane = tid & 31;
    const int wm   = wid & 1;        // 0..1 -> 64 rows
    const int wn   = wid >> 1;       // 0..3 -> 32 cols
    const int m0   = blockIdx.y * 128;
    const int n0   = blockIdx.x * 128;

    const __nv_bfloat16* aHi = Ahi + (size_t)m0 * Kdim;
    const __nv_bfloat16* aLo = Alo + (size_t)m0 * Kdim;
    const __nv_bfloat16* bHi = Bhi + (size_t)n0 * Kdim;
    const __nv_bfloat16* bLo = Blo + (size_t)n0 * Kdim;

    // A x4: rows (lane&15), k-seg (lane>>4)*16
    const int aRow = wm * 64 + (lane & 15);
    const uint32_t aKadd = (uint32_t)((lane >> 4) << 4);
    // B x4: rows wn*32 + pr*16 + ((lane>>4)&1)*8 + (lane&7), k-seg ((lane>>3)&1)*16
    const int bRowB = wn * 32 + ((lane >> 4) & 1) * 8 + (lane & 7);
    const uint32_t bKadd = (uint32_t)(((lane >> 3) & 1) << 4);

    float c[4][4][4];
#pragma unroll
    for (int mi = 0; mi < 4; mi++)
#pragma unroll
        for (int ni = 0; ni < 4; ni++)
#pragma unroll
            for (int e = 0; e < 4; e++) c[mi][ni][e] = 0.f;

    const int nch = Kdim >> 5;       // K-chunks of 32
    load_chunk32(sb, 0, aHi, aLo, bHi, bLo, 0, Kdim, tid);

    for (int t = 0; t < nch; t++) {
        if (t + 1 < nch) {
            load_chunk32(sb, (t + 1) & 1, aHi, aLo, bHi, bLo, (t + 1) << 5, Kdim, tid);
            CP_WAIT1();
        } else {
            CP_WAIT0();
        }
        __syncthreads();

        const uint32_t st  = sb + (uint32_t)(t & 1) * GK_STAGE;
        const uint32_t tAh = st;
        const uint32_t tAl = st + 8192u;
        const uint32_t tBh = st + 16384u;
        const uint32_t tBl = st + 24576u;

#pragma unroll
        for (int ks = 0; ks < 2; ks++) {
            // preload B fragments for this k16 slice (2 pr groups of 16 rows)
            uint32_t bh4[2][4], bl4[2][4];
#pragma unroll
            for (int pr = 0; pr < 2; pr++) {
                const int br = bRowB + pr * 16;
                const uint32_t bOff = SW64(br, ((uint32_t)(ks * 32) + bKadd));
                LDSM_X4(bh4[pr], tBh + bOff);
                LDSM_X4(bl4[pr], tBl + bOff);
            }
#pragma unroll
            for (int mi = 0; mi < 4; mi++) {
                const int ar = aRow + mi * 16;
                const uint32_t aOff = SW64(ar, ((uint32_t)(ks * 32) + aKadd));
                uint32_t ah[4], al[4];
                LDSM_X4(ah, tAh + aOff);
                LDSM_X4(al, tAl + aOff);
                // pass 1: ah*bh (acc distance 4)
                MMA16816(c[mi][0], ah, bh4[0][0], bh4[0][1]);
                MMA16816(c[mi][1], ah, bh4[0][2], bh4[0][3]);
                MMA16816(c[mi][2], ah, bh4[1][0], bh4[1][1]);
                MMA16816(c[mi][3], ah, bh4[1][2], bh4[1][3]);
                // pass 2: ah*bl
                MMA16816(c[mi][0], ah, bl4[0][0], bl4[0][1]);
                MMA16816(c[mi][1], ah, bl4[0][2], bl4[0][3]);
                MMA16816(c[mi][2], ah, bl4[1][0], bl4[1][1]);
                MMA16816(c[mi][3], ah, bl4[1][2], bl4[1][3]);
                // pass 3: al*bh
                MMA16816(c[mi][0], al, bh4[0][0], bh4[0][1]);
                MMA16816(c[mi][1], al, bh4[0][2], bh4[0][3]);
                MMA16816(c[mi][2], al, bh4[1][0], bh4[1][1]);
                MMA16816(c[mi][3], al, bh4[1][2], bh4[1][3]);
            }
        }
        __syncthreads();
    }

    const int lr = lane >> 2;
    const int lc = (lane & 3) * 2;

    if (MODE == 0) {
#pragma unroll
        for (int mi = 0; mi < 4; mi++) {
            const int r0 = m0 + wm * 64 + mi * 16 + lr;
#pragma unroll
            for (int ni = 0; ni < 4; ni++) {
                const int col = n0 + wn * 32 + ni * 8 + lc;
                const float b0 = bias[col], b1 = bias[col + 1];
                float2 v0, v1;
                v0.x = c[mi][ni][0] + b0; v0.y = c[mi][ni][1] + b1;
                v1.x = c[mi][ni][2] + b0; v1.y = c[mi][ni][3] + b1;
                *(float2*)&Cm[(size_t)r0 * Ndim + col]       = v0;
                *(float2*)&Cm[(size_t)(r0 + 8) * Ndim + col] = v1;
            }
        }
    } else {
        // QKV epilogue: write hi/lo bf16 head-major [(b*H+h)*T + t]*D + d
        const int colbase = n0 + wn * 32;
        const int region  = colbase >> 11;          // 0=Q,1=K,2=V
        const int cr      = colbase & 2047;
        const int hh      = cr >> 7;
        const int dbase   = cr & 127;               // 0,32,64,96
        const float scale = (region == 0) ? SC_Q : 1.f;
        __nv_bfloat16 *dh, *dl;
        if (region == 0)      { dh = qhi; dl = qlo; }
        else if (region == 1) { dh = khi; dl = klo; }
        else                  { dh = vhi; dl = vlo; }
#pragma unroll
        for (int mi = 0; mi < 4; mi++) {
            const int r0 = m0 + wm * 64 + mi * 16 + lr;   // token index b*T + t
#pragma unroll
            for (int half = 0; half < 2; half++) {
                const int row = r0 + half * 8;
                const int bb  = row >> 11;
                const int tt  = row & 2047;
                const size_t base = (((size_t)(bb * H_ + hh)) * T_ + tt) * D_ + dbase;
#pragma unroll
                for (int ni = 0; ni < 4; ni++) {
                    const int col = colbase + ni * 8 + lc;
                    float v0 = (c[mi][ni][2 * half]     + bias[col])     * scale;
                    float v1 = (c[mi][ni][2 * half + 1] + bias[col + 1]) * scale;
                    uint32_t hv, lv;
                    split2(v0, v1, hv, lv);
                    *(uint32_t*)&dh[base + ni * 8 + lc] = hv;
                    *(uint32_t*)&dl[base + ni * 8 + lc] = lv;
                }
            }
        }
    }
}

// ---------------------------------------------------------------------------
// Flash attention (unchanged from round 6): register softmax, bf16 hi/lo
// operands from gmem, double-buffered cp.async K/V pipeline.
// ---------------------------------------------------------------------------
#define FQ_HI 0u
#define FQ_LO 32768u
#define FKV0  65536u
#define FKV_STAGE 65536u
#define FL_SMEM 196608

__device__ __forceinline__ void flash_load_kv(uint32_t sb, uint32_t stage,
                                              const __nv_bfloat16* kh_g,
                                              const __nv_bfloat16* kl_g,
                                              const __nv_bfloat16* vh_g,
                                              const __nv_bfloat16* vl_g,
                                              int j0, int tid)
{
    const __nv_bfloat16* srcs[4] = {
        kh_g + (size_t)j0 * D_, kl_g + (size_t)j0 * D_,
        vh_g + (size_t)j0 * D_, vl_g + (size_t)j0 * D_
    };
#pragma unroll
    for (int l = 0; l < 16; l++) {
        int idx  = tid + l * 256;
        int tile = idx >> 10;
        int rem  = idx & 1023;
        int row  = rem >> 4;
        int seg  = rem & 15;
        CP_ASYNC16(sb + stage + (uint32_t)(tile * 16384) +
                       (uint32_t)(row * 256 + ((seg * 16) ^ ((row & 7) << 4))),
                   srcs[tile] + (size_t)row * D_ + seg * 8);
    }
    CP_COMMIT();
}

__global__ __launch_bounds__(256, 1)
void flash_reg(const __nv_bfloat16* __restrict__ qhi, const __nv_bfloat16* __restrict__ qlo,
               const __nv_bfloat16* __restrict__ khi, const __nv_bfloat16* __restrict__ klo,
               const __nv_bfloat16* __restrict__ vhi, const __nv_bfloat16* __restrict__ vlo,
               __nv_bfloat16* __restrict__ ahi, __nv_bfloat16* __restrict__ alo)
{
    extern __shared__ __align__(1024) char smf[];
    const uint32_t sb = smem_u32(smf);

    const int tid  = threadIdx.x;
    const int wid  = tid >> 5, lane = tid & 31;
    const int lr   = lane >> 2;
    const int lc   = (lane & 3) << 1;
    const int b    = blockIdx.x >> 4, h = blockIdx.x & 15;
    const int i0   = ((int)gridDim.y - 1 - (int)blockIdx.y) * 128;

    const size_t headoff = ((size_t)(b * H_ + h)) * T_ * D_;
    const __nv_bfloat16* qh_g = qhi + headoff + (size_t)i0 * D_;
    const __nv_bfloat16* ql_g = qlo + headoff + (size_t)i0 * D_;
    const __nv_bfloat16* kh_g = khi + headoff;
    const __nv_bfloat16* kl_g = klo + headoff;
    const __nv_bfloat16* vh_g = vhi + headoff;
    const __nv_bfloat16* vl_g = vlo + headoff;

    {
        const __nv_bfloat16* srcs[2] = { qh_g, ql_g };
#pragma unroll
        for (int l = 0; l < 16; l++) {
            int idx  = tid + l * 256;
            int tile = idx >> 11;
            int rem  = idx & 2047;
            int row  = rem >> 4;
            int seg  = rem & 15;
            CP_ASYNC16(sb + (uint32_t)(tile * 32768) +
                           (uint32_t)(row * 256 + ((seg * 16) ^ ((row & 7) << 4))),
                       srcs[tile] + (size_t)row * D_ + seg * 8);
        }
    }
    flash_load_kv(sb, FKV0, kh_g, kl_g, vh_g, vl_g, 0, tid);

    float o[16][4];
#pragma unroll
    for (int ni = 0; ni < 16; ni++)
#pragma unroll
        for (int e = 0; e < 4; e++) o[ni][e] = 0.f;
    float m0r = -1e30f, m1r = -1e30f, L0 = 0.f, L1 = 0.f;

    const uint32_t kxor  = (uint32_t)((lane & 7) << 4);
    const uint32_t aKadd = (uint32_t)((lane >> 4) << 4);
    const uint32_t qRow  = (uint32_t)((wid * 16 + (lane & 15)) * 256);
    const uint32_t kRowB = (uint32_t)((((lane >> 4) & 1) * 8 + (lane & 7)) * 256);
    const uint32_t bKadd = (uint32_t)(((lane >> 3) & 1) << 4);
    const uint32_t vRowB = (uint32_t)((lane & 15) * 256);
    const uint32_t vCadd = (uint32_t)(((lane >> 4) & 1) * 16);

    const int ntiles = i0 / 64 + 2;
    for (int jt = 0; jt < ntiles; jt++) {
        const int j0 = jt * 64;
        if (jt + 1 < ntiles) {
            flash_load_kv(sb, FKV0 + (uint32_t)((jt + 1) & 1) * FKV_STAGE,
                          kh_g, kl_g, vh_g, vl_g, (jt + 1) * 64, tid);
            CP_WAIT1();
        } else {
            CP_WAIT0();
        }
        __syncthreads();

        const uint32_t stg   = FKV0 + (uint32_t)(jt & 1) * FKV_STAGE;
        const uint32_t sKhi  = stg;
        const uint32_t sKlo  = stg + 16384u;
        const uint32_t sVhi  = stg + 32768u;
        const uint32_t sVlo  = stg + 49152u;

        float s[8][4];
#pragma unroll
        for (int ni = 0; ni < 8; ni++)
#pragma unroll
            for (int e = 0; e < 4; e++) s[ni][e] = 0.f;

#pragma unroll
        for (int ks = 0; ks < 8; ks++) {
            const uint32_t ak = ((uint32_t)(ks * 32) + aKadd) ^ kxor;
            const uint32_t bk = ((uint32_t)(ks * 32) + bKadd) ^ kxor;
            uint32_t qh[4], ql[4];
            LDSM_X4(qh, sb + FQ_HI + qRow + ak);
            LDSM_X4(ql, sb + FQ_LO + qRow + ak);
#pragma unroll
            for (int n2 = 0; n2 < 4; n2++) {
                uint32_t kh4[4], kl4[4];
                LDSM_X4(kh4, sb + sKhi + kRowB + (uint32_t)(n2 * 4096) + bk);
                LDSM_X4(kl4, sb + sKlo + kRowB + (uint32_t)(n2 * 4096) + bk);
                MMA16816(s[2 * n2],     qh, kh4[0], kh4[1]);
                MMA16816(s[2 * n2 + 1], qh, kh4[2], kh4[3]);
                MMA16816(s[2 * n2],     qh, kl4[0], kl4[1]);
                MMA16816(s[2 * n2 + 1], qh, kl4[2], kl4[3]);
                MMA16816(s[2 * n2],     ql, kh4[0], kh4[1]);
                MMA16816(s[2 * n2 + 1], ql, kh4[2], kh4[3]);
            }
        }

        if (jt >= ntiles - 2) {
            const int r0 = i0 + wid * 16 + lr;
#pragma unroll
            for (int ni = 0; ni < 8; ni++) {
                int cc = j0 + ni * 8 + lc;
                if (cc     > r0)     s[ni][0] = -1e30f;
                if (cc + 1 > r0)     s[ni][1] = -1e30f;
                if (cc     > r0 + 8) s[ni][2] = -1e30f;
                if (cc + 1 > r0 + 8) s[ni][3] = -1e30f;
            }
        }

        float mx0 = -1e30f, mx1 = -1e30f;
#pragma unroll
        for (int ni = 0; ni < 8; ni++) {
            mx0 = fmaxf(mx0, fmaxf(s[ni][0], s[ni][1]));
            mx1 = fmaxf(mx1, fmaxf(s[ni][2], s[ni][3]));
        }
        mx0 = fmaxf(mx0, __shfl_xor_sync(0xffffffffu, mx0, 1));
        mx0 = fmaxf(mx0, __shfl_xor_sync(0xffffffffu, mx0, 2));
        mx1 = fmaxf(mx1, __shfl_xor_sync(0xffffffffu, mx1, 1));
        mx1 = fmaxf(mx1, __shfl_xor_sync(0xffffffffu, mx1, 2));
        const float mn0 = fmaxf(m0r, mx0);
        const float mn1 = fmaxf(m1r, mx1);
        const float co0 = exp2f(m0r - mn0);
        const float co1 = exp2f(m1r - mn1);
        m0r = mn0; m1r = mn1;

        float sum0 = 0.f, sum1 = 0.f;
#pragma unroll
        for (int ni = 0; ni < 8; ni++) {
            float e0 = exp2f(s[ni][0] - mn0);
            float e1 = exp2f(s[ni][1] - mn0);
            float e2 = exp2f(s[ni][2] - mn1);
            float e3 = exp2f(s[ni][3] - mn1);
            sum0 += e0 + e1; sum1 += e2 + e3;
            s[ni][0] = e0; s[ni][1] = e1; s[ni][2] = e2; s[ni][3] = e3;
        }
        sum0 += __shfl_xor_sync(0xffffffffu, sum0, 1);
        sum0 += __shfl_xor_sync(0xffffffffu, sum0, 2);
        sum1 += __shfl_xor_sync(0xffffffffu, sum1, 1);
        sum1 += __shfl_xor_sync(0xffffffffu, sum1, 2);
        L0 = L0 * co0 + sum0;
        L1 = L1 * co1 + sum1;

#pragma unroll
        for (int ni = 0; ni < 16; ni++) {
            o[ni][0] *= co0; o[ni][1] *= co0;
            o[ni][2] *= co1; o[ni][3] *= co1;
        }

#pragma unroll
        for (int kb = 0; kb < 4; kb++) {
            uint32_t ph[4], pl[4];
            split2(s[2 * kb][0],     s[2 * kb][1],     ph[0], pl[0]);
            split2(s[2 * kb][2],     s[2 * kb][3],     ph[1], pl[1]);
            split2(s[2 * kb + 1][0], s[2 * kb + 1][1], ph[2], pl[2]);
            split2(s[2 * kb + 1][2], s[2 * kb + 1][3], ph[3], pl[3]);
            const uint32_t vrb = (uint32_t)(kb * 16 * 256) + vRowB;
#pragma unroll
            for (int n2 = 0; n2 < 8; n2++) {
                uint32_t vh4[4], vl4[4];
                const uint32_t cbo = (((uint32_t)(n2 * 32) + vCadd) ^ kxor);
                LDSM_X4_T(vh4, sb + sVhi + vrb + cbo);
                LDSM_X4_T(vl4, sb + sVlo + vrb + cbo);
                MMA16816(o[2 * n2],     ph, vh4[0], vh4[1]);
                MMA16816(o[2 * n2 + 1], ph, vh4[2], vh4[3]);
                MMA16816(o[2 * n2],     ph, vl4[0], vl4[1]);
                MMA16816(o[2 * n2 + 1], ph, vl4[2], vl4[3]);
                MMA16816(o[2 * n2],     pl, vh4[0], vh4[1]);
                MMA16816(o[2 * n2 + 1], pl, vh4[2], vh4[3]);
            }
        }
        __syncthreads();
    }

    {
        const float i0v = 1.f / L0;
        const float i1v = 1.f / L1;
        const size_t ra = (size_t)(b * T_ + i0 + wid * 16 + lr) * C_ + h * D_;
        const size_t rb = ra + (size_t)8 * C_;
#pragma unroll
        for (int ni = 0; ni < 16; ni++) {
            uint32_t hv, lv;
            split2(o[ni][0] * i0v, o[ni][1] * i0v, hv, lv);
            *(uint32_t*)&ahi[ra + ni * 8 + lc] = hv;
            *(uint32_t*)&alo[ra + ni * 8 + lc] = lv;
            split2(o[ni][2] * i1v, o[ni][3] * i1v, hv, lv);
            *(uint32_t*)&ahi[rb + ni * 8 + lc] = hv;
            *(uint32_t*)&alo[rb + ni * 8 + lc] = lv;
        }
    }
}

// ---------------------------------------------------------------------------
// Launch
// ---------------------------------------------------------------------------
extern "C" void kernel_launch(void* const* d_in, const int* in_sizes, int n_in,
                              void* d_out, int out_size)
{
    const float* x     = (const float*)d_in[0];
    const float* Wqkv  = (const float*)d_in[1];
    const float* bqkv  = (const float*)d_in[2];
    const float* Wproj = (const float*)d_in[3];
    const float* bproj = (const float*)d_in[4];
    float* out = (float*)d_out;

    __nv_bfloat16 *xhi, *xlo, *w1hi, *w1lo, *w2hi, *w2lo;
    __nv_bfloat16 *qhi, *qlo, *khi, *klo, *vhi, *vlo, *ahi, *alo;
    cudaGetSymbolAddress((void**)&xhi,  g_xhi);
    cudaGetSymbolAddress((void**)&xlo,  g_xlo);
    cudaGetSymbolAddress((void**)&w1hi, g_w1hi);
    cudaGetSymbolAddress((void**)&w1lo, g_w1lo);
    cudaGetSymbolAddress((void**)&w2hi, g_w2hi);
    cudaGetSymbolAddress((void**)&w2lo, g_w2lo);
    cudaGetSymbolAddress((void**)&qhi,  g_qhi);
    cudaGetSymbolAddress((void**)&qlo,  g_qlo);
    cudaGetSymbolAddress((void**)&khi,  g_khi);
    cudaGetSymbolAddress((void**)&klo,  g_klo);
    cudaGetSymbolAddress((void**)&vhi,  g_vhi);
    cudaGetSymbolAddress((void**)&vlo,  g_vlo);
    cudaGetSymbolAddress((void**)&ahi,  g_ahi);
    cudaGetSymbolAddress((void**)&alo,  g_alo);

    cudaFuncSetAttribute(mma_gemm<0>, cudaFuncAttributeMaxDynamicSharedMemorySize,
                         GEMM_SMEM);
    cudaFuncSetAttribute(mma_gemm<1>, cudaFuncAttributeMaxDynamicSharedMemorySize,
                         GEMM_SMEM);
    cudaFuncSetAttribute(flash_reg, cudaFuncAttributeMaxDynamicSharedMemorySize,
                         FL_SMEM);

    const int n4x = (M_ * C_) / 4;

    split_kernel<<<n4x / 256, 256>>>(x, xhi, xlo, n4x);
    split_transpose_kernel<<<dim3(N1_ / 32, C_ / 32), dim3(32, 8)>>>(Wqkv, w1hi, w1lo, C_, N1_);
    split_transpose_kernel<<<dim3(C_ / 32, C_ / 32), dim3(32, 8)>>>(Wproj, w2hi, w2lo, C_, C_);

    // 1) QKV GEMM -> split bf16 Q(scaled)/K/V head-major
    mma_gemm<1><<<dim3(N1_ / 128, M_ / 128), 256, GEMM_SMEM>>>(
        xhi, xlo, w1hi, w1lo, bqkv, nullptr,
        qhi, qlo, khi, klo, vhi, vlo, N1_, C_);

    // 2) causal flash attention -> split bf16 att
    flash_reg<<<dim3(B_ * H_, T_ / 128), 256, FL_SMEM>>>(
        qhi, qlo, khi, klo, vhi, vlo, ahi, alo);

    // 3) proj GEMM -> fp32 out
    mma_gemm<0><<<dim3(C_ / 128, M_ / 128), 256, GEMM_SMEM>>>(
        ahi, alo, w2hi, w2lo, bproj, out,
        nullptr, nullptr, nullptr, nullptr, nullptr, nullptr, C_, C_);
}